// round 2
// baseline (speedup 1.0000x reference)
#include <cuda_runtime.h>
#include <cuda_bf16.h>

#define N_MAX    50000
#define E_MAX    1600000
#define HEADS    8
#define HD       32
#define FDIM     256          // HEADS*HD == F_IN == HID
#define SLOPE    0.2f
#define LN_EPS   1e-5f

// ---------------- scratch (device globals; no allocation allowed) ----------
__device__ float    g_H   [N_MAX * FDIM];   // h per node, [n][head*32+d]
__device__ float    g_si  [N_MAX * HEADS];
__device__ float    g_sj  [N_MAX * HEADS];
__device__ unsigned g_m   [N_MAX * HEADS];  // encoded segment max
__device__ float    g_den [N_MAX * HEADS];
__device__ float    g_e   [E_MAX * HEADS];  // edge scores, then exp values
__device__ float    g_agg [N_MAX * FDIM];
__device__ float    g_mean[N_MAX * HD];

// monotone float<->uint encoding for atomicMax on floats (incl. negatives)
__device__ __forceinline__ unsigned fenc(float f) {
    unsigned u = __float_as_uint(f);
    return (u & 0x80000000u) ? ~u : (u | 0x80000000u);
}
__device__ __forceinline__ float fdec(unsigned u) {
    return (u & 0x80000000u) ? __uint_as_float(u ^ 0x80000000u)
                             : __uint_as_float(~u);
}

// ---------------- K0: zero scratch -----------------------------------------
__global__ void k_init(int N) {
    int i = blockIdx.x * 256 + threadIdx.x;
    if (i < N * FDIM) g_agg[i] = 0.f;
    if (i < N * HEADS) { g_den[i] = 0.f; g_m[i] = 0u; }
}

// ---------------- K1: H = X @ Wf + bw  (128x128x16 tiled fp32 GEMM) --------
// Wf[k][c] = W[(c>>5)*F_IN*HD + k*HD + (c&31)],  c = head*32 + d
__global__ void __launch_bounds__(256)
k_gemm_h(const float* __restrict__ X, const float* __restrict__ W,
         const float* __restrict__ bw, int N) {
    __shared__ float As[16][132];
    __shared__ float Bs[16][132];
    const int tid  = threadIdx.x;
    const int row0 = blockIdx.y * 128;
    const int col0 = blockIdx.x * 128;
    const int tr   = (tid >> 4) * 8;
    const int tcb  = (tid & 15) * 8;

    float acc[8][8];
#pragma unroll
    for (int i = 0; i < 8; i++)
#pragma unroll
        for (int j = 0; j < 8; j++) acc[i][j] = 0.f;

    for (int k0 = 0; k0 < FDIM; k0 += 16) {
        // load X tile: 128 rows x 16 k  (512 float4, 2 per thread)
#pragma unroll
        for (int it = 0; it < 2; it++) {
            int v = tid + 256 * it;
            int r = v >> 2, kk = (v & 3) << 2;
            float4 xv = make_float4(0.f, 0.f, 0.f, 0.f);
            if (row0 + r < N)
                xv = *(const float4*)&X[(size_t)(row0 + r) * FDIM + k0 + kk];
            As[kk + 0][r] = xv.x; As[kk + 1][r] = xv.y;
            As[kk + 2][r] = xv.z; As[kk + 3][r] = xv.w;
        }
        // load W tile: 16 k x 128 c  (512 float4, 2 per thread)
#pragma unroll
        for (int it = 0; it < 2; it++) {
            int v = tid + 256 * it;
            int k = v >> 5, c4 = (v & 31) << 2;
            int c = col0 + c4;
            const float4 wv = *(const float4*)
                &W[(size_t)(c >> 5) * FDIM * HD + (size_t)(k0 + k) * HD + (c & 31)];
            *(float4*)&Bs[k][c4] = wv;
        }
        __syncthreads();
#pragma unroll
        for (int kk = 0; kk < 16; kk++) {
            float a[8], b[8];
            *(float4*)&a[0] = *(const float4*)&As[kk][tr];
            *(float4*)&a[4] = *(const float4*)&As[kk][tr + 4];
            *(float4*)&b[0] = *(const float4*)&Bs[kk][tcb];
            *(float4*)&b[4] = *(const float4*)&Bs[kk][tcb + 4];
#pragma unroll
            for (int i = 0; i < 8; i++)
#pragma unroll
                for (int j = 0; j < 8; j++) acc[i][j] += a[i] * b[j];
        }
        __syncthreads();
    }
    // epilogue: + bw, store
#pragma unroll
    for (int i = 0; i < 8; i++) {
        int row = row0 + tr + i;
        if (row >= N) break;
#pragma unroll
        for (int j = 0; j < 8; j++) {
            int c = col0 + tcb + j;
            g_H[(size_t)row * FDIM + c] = acc[i][j] + bw[c];
        }
    }
}

// ---------------- K2: si/sj per (node, head) — warp per head ---------------
__global__ void k_scores(const float* __restrict__ A, int N) {
    int n = blockIdx.x;
    if (n >= N) return;
    int h    = threadIdx.x >> 5;
    int lane = threadIdx.x & 31;
    float x  = g_H[(size_t)n * FDIM + h * HD + lane];
    float s1 = x * A[h * 2 * HD + lane];
    float s2 = x * A[h * 2 * HD + HD + lane];
#pragma unroll
    for (int o = 16; o; o >>= 1) {
        s1 += __shfl_xor_sync(0xffffffffu, s1, o);
        s2 += __shfl_xor_sync(0xffffffffu, s2, o);
    }
    if (lane == 0) {
        g_si[n * HEADS + h] = s1;
        g_sj[n * HEADS + h] = s2;
    }
}

// ---------------- K3: edge scores + segment max -----------------------------
__global__ void k_edge_max(const int* __restrict__ EI,
                           const float* __restrict__ ba, int E) {
    int gid = blockIdx.x * 256 + threadIdx.x;
    if (gid >= E * HEADS) return;
    int e = gid >> 3, h = gid & 7;
    int tgt = EI[e], src = EI[E + e];
    float sc = g_si[tgt * HEADS + h] + g_sj[src * HEADS + h] + ba[h];
    sc = (sc >= 0.f) ? sc : SLOPE * sc;
    g_e[gid] = sc;
    atomicMax(&g_m[tgt * HEADS + h], fenc(sc));
}

// ---------------- K4: exp + segment sum -------------------------------------
__global__ void k_edge_exp(const int* __restrict__ EI, int E) {
    int gid = blockIdx.x * 256 + threadIdx.x;
    if (gid >= E * HEADS) return;
    int e = gid >> 3, h = gid & 7;
    int tgt = EI[e];
    float m  = fdec(g_m[tgt * HEADS + h]);
    float ex = expf(g_e[gid] - m);
    g_e[gid] = ex;
    atomicAdd(&g_den[tgt * HEADS + h], ex);
}

// ---------------- K5: weighted message scatter (warp per edge) --------------
__global__ void k_edge_agg(const int* __restrict__ EI, int E) {
    int widx = (blockIdx.x * 256 + threadIdx.x) >> 5;
    if (widx >= E) return;
    int lane = threadIdx.x & 31;
    int tgt = EI[widx], src = EI[E + widx];
    int h0 = lane >> 3;                                   // head for first half
    float a0 = g_e[(size_t)widx * 8 + h0]     / g_den[tgt * HEADS + h0];
    float a1 = g_e[(size_t)widx * 8 + h0 + 4] / g_den[tgt * HEADS + h0 + 4];
    const float4* hs = (const float4*)&g_H[(size_t)src * FDIM];
    float4 v0 = hs[lane];       // channels lane*4..+3       (head = lane>>3)
    float4 v1 = hs[32 + lane];  // channels 128+lane*4..+3   (head = 4+lane>>3)
    float4* ag = (float4*)&g_agg[(size_t)tgt * FDIM];
    asm volatile("red.global.add.v4.f32 [%0], {%1,%2,%3,%4};"
                 :: "l"(ag + lane),
                    "f"(a0 * v0.x), "f"(a0 * v0.y), "f"(a0 * v0.z), "f"(a0 * v0.w)
                 : "memory");
    asm volatile("red.global.add.v4.f32 [%0], {%1,%2,%3,%4};"
                 :: "l"(ag + 32 + lane),
                    "f"(a1 * v1.x), "f"(a1 * v1.y), "f"(a1 * v1.z), "f"(a1 * v1.w)
                 : "memory");
}

// ---------------- K6: skip + ELU + LayerNorm + head-mean --------------------
__global__ void k_node(const float* __restrict__ gamma,
                       const float* __restrict__ beta, int N) {
    int n = blockIdx.x;
    if (n >= N) return;
    int c    = threadIdx.x;           // head*32 + d
    int lane = c & 31;
    float v = g_agg[(size_t)n * FDIM + c] + g_H[(size_t)n * FDIM + c];
    v = (v > 0.f) ? v : expm1f(v);
    float s = v, ss = v * v;
#pragma unroll
    for (int o = 16; o; o >>= 1) {
        s  += __shfl_xor_sync(0xffffffffu, s, o);
        ss += __shfl_xor_sync(0xffffffffu, ss, o);
    }
    float mu  = s * (1.f / HD);
    float var = ss * (1.f / HD) - mu * mu;
    float nrm = (v - mu) * rsqrtf(var + LN_EPS) * gamma[c] + beta[c];
    __shared__ float sm[FDIM];
    sm[c] = nrm;
    __syncthreads();
    if (threadIdx.x < HD) {
        float m = 0.f;
#pragma unroll
        for (int h = 0; h < HEADS; h++) m += sm[h * HD + lane];
        g_mean[(size_t)n * HD + lane] = m * (1.f / HEADS);
    }
}

// ---------------- K7: out = ELU(mean @ Wout + bout) -------------------------
__global__ void k_out(const float* __restrict__ Wout,
                      const float* __restrict__ bout,
                      float* __restrict__ out, int N) {
    __shared__ float sm[32][33];
    int row0 = blockIdx.x * 32;
    int tid  = threadIdx.x;
    for (int i = tid; i < 1024; i += 256) {
        int r = i >> 5, d = i & 31;
        sm[r][d] = (row0 + r < N) ? g_mean[(size_t)(row0 + r) * HD + d] : 0.f;
    }
    __syncthreads();
    int col = tid;
    float w[32];
#pragma unroll
    for (int d = 0; d < 32; d++) w[d] = Wout[d * FDIM + col];
    float b = bout[col];
    for (int r = 0; r < 32; r++) {
        if (row0 + r >= N) break;
        float acc = b;
#pragma unroll
        for (int d = 0; d < 32; d++) acc += sm[r][d] * w[d];
        acc = (acc > 0.f) ? acc : expm1f(acc);
        out[(size_t)(row0 + r) * FDIM + col] = acc;
    }
}

// ---------------- launch -----------------------------------------------------
extern "C" void kernel_launch(void* const* d_in, const int* in_sizes, int n_in,
                              void* d_out, int out_size) {
    const float* X    = (const float*)d_in[0];
    const int*   EI   = (const int*)  d_in[1];
    const float* W    = (const float*)d_in[2];
    const float* bw   = (const float*)d_in[3];
    const float* A    = (const float*)d_in[4];
    const float* ba   = (const float*)d_in[5];
    const float* gmm  = (const float*)d_in[6];
    const float* bet  = (const float*)d_in[7];
    const float* Wout = (const float*)d_in[8];
    const float* bout = (const float*)d_in[9];
    float* out = (float*)d_out;

    const int N = in_sizes[0] / FDIM;
    const int E = in_sizes[1] / 2;

    // K0: zero scratch
    k_init<<<(N * FDIM + 255) / 256, 256>>>(N);
    // K1: feature GEMM
    {
        dim3 grid(FDIM / 128, (N + 127) / 128);
        k_gemm_h<<<grid, 256>>>(X, W, bw, N);
    }
    // K2: attention pre-scores
    k_scores<<<N, 256>>>(A, N);
    // K3: edge scores + segment max
    k_edge_max<<<(E * HEADS + 255) / 256, 256>>>(EI, ba, E);
    // K4: exp + segment sum
    k_edge_exp<<<(E * HEADS + 255) / 256, 256>>>(EI, E);
    // K5: weighted scatter (warp per edge)
    k_edge_agg<<<(E + 7) / 8, 256>>>(EI, E);
    // K6: skip + ELU + LN + head mean
    k_node<<<N, 256>>>(gmm, bet, N);
    // K7: final projection + ELU
    k_out<<<(N + 31) / 32, 256>>>(Wout, bout, out, N);
}

// round 3
// speedup vs baseline: 1.1338x; 1.1338x over previous
#include <cuda_runtime.h>
#include <cuda_bf16.h>

#define N_MAX    50000
#define E_MAX    1600000
#define HEADS    8
#define HD       32
#define FDIM     256          // HEADS*HD == F_IN == HID
#define SLOPE    0.2f
#define LN_EPS   1e-5f

// ---------------- scratch (device globals; no allocation allowed) ----------
__device__ float    g_H   [N_MAX * FDIM];   // h per node, [n][head*32+d]
__device__ float    g_si  [N_MAX * HEADS];
__device__ float    g_sj  [N_MAX * HEADS];
__device__ float    g_mean[N_MAX * HD];
__device__ int      g_deg [N_MAX];
__device__ int      g_off [N_MAX];
__device__ int      g_cur [N_MAX];
__device__ int      g_csrc[E_MAX];          // CSR: src per slot
__device__ float    g_ex  [E_MAX * HEADS];  // CSR-ordered exp(score) per head

// ---------------- K0: zero degree counters ---------------------------------
__global__ void k_zero(int N) {
    int i = blockIdx.x * 256 + threadIdx.x;
    if (i < N) g_deg[i] = 0;
}

// ---------------- K1: H = X @ Wf + bw  (128x128x16 tiled fp32 GEMM) --------
__global__ void __launch_bounds__(256)
k_gemm_h(const float* __restrict__ X, const float* __restrict__ W,
         const float* __restrict__ bw, int N) {
    __shared__ float As[16][132];
    __shared__ float Bs[16][132];
    const int tid  = threadIdx.x;
    const int row0 = blockIdx.y * 128;
    const int col0 = blockIdx.x * 128;
    const int tr   = (tid >> 4) * 8;
    const int tcb  = (tid & 15) * 8;

    float acc[8][8];
#pragma unroll
    for (int i = 0; i < 8; i++)
#pragma unroll
        for (int j = 0; j < 8; j++) acc[i][j] = 0.f;

    for (int k0 = 0; k0 < FDIM; k0 += 16) {
#pragma unroll
        for (int it = 0; it < 2; it++) {
            int v = tid + 256 * it;
            int r = v >> 2, kk = (v & 3) << 2;
            float4 xv = make_float4(0.f, 0.f, 0.f, 0.f);
            if (row0 + r < N)
                xv = *(const float4*)&X[(size_t)(row0 + r) * FDIM + k0 + kk];
            As[kk + 0][r] = xv.x; As[kk + 1][r] = xv.y;
            As[kk + 2][r] = xv.z; As[kk + 3][r] = xv.w;
        }
#pragma unroll
        for (int it = 0; it < 2; it++) {
            int v = tid + 256 * it;
            int k = v >> 5, c4 = (v & 31) << 2;
            int c = col0 + c4;
            const float4 wv = *(const float4*)
                &W[(size_t)(c >> 5) * FDIM * HD + (size_t)(k0 + k) * HD + (c & 31)];
            *(float4*)&Bs[k][c4] = wv;
        }
        __syncthreads();
#pragma unroll
        for (int kk = 0; kk < 16; kk++) {
            float a[8], b[8];
            *(float4*)&a[0] = *(const float4*)&As[kk][tr];
            *(float4*)&a[4] = *(const float4*)&As[kk][tr + 4];
            *(float4*)&b[0] = *(const float4*)&Bs[kk][tcb];
            *(float4*)&b[4] = *(const float4*)&Bs[kk][tcb + 4];
#pragma unroll
            for (int i = 0; i < 8; i++)
#pragma unroll
                for (int j = 0; j < 8; j++) acc[i][j] += a[i] * b[j];
        }
        __syncthreads();
    }
#pragma unroll
    for (int i = 0; i < 8; i++) {
        int row = row0 + tr + i;
        if (row >= N) break;
#pragma unroll
        for (int j = 0; j < 8; j++) {
            int c = col0 + tcb + j;
            g_H[(size_t)row * FDIM + c] = acc[i][j] + bw[c];
        }
    }
}

// ---------------- K2: si/sj per (node, head) — warp per head ---------------
__global__ void k_scores(const float* __restrict__ A, int N) {
    int n = blockIdx.x;
    if (n >= N) return;
    int h    = threadIdx.x >> 5;
    int lane = threadIdx.x & 31;
    float x  = g_H[(size_t)n * FDIM + h * HD + lane];
    float s1 = x * A[h * 2 * HD + lane];
    float s2 = x * A[h * 2 * HD + HD + lane];
#pragma unroll
    for (int o = 16; o; o >>= 1) {
        s1 += __shfl_xor_sync(0xffffffffu, s1, o);
        s2 += __shfl_xor_sync(0xffffffffu, s2, o);
    }
    if (lane == 0) {
        g_si[n * HEADS + h] = s1;
        g_sj[n * HEADS + h] = s2;
    }
}

// ---------------- K3: degree histogram --------------------------------------
__global__ void k_hist(const int* __restrict__ EI, int E) {
    int e = blockIdx.x * 256 + threadIdx.x;
    if (e < E) atomicAdd(&g_deg[EI[e]], 1);
}

// ---------------- K4: exclusive scan (single block, 1024 threads) -----------
__global__ void __launch_bounds__(1024)
k_scan(int N) {
    __shared__ int wsum[32];
    __shared__ int carry_s;
    int tid = threadIdx.x, lane = tid & 31, wid = tid >> 5;
    if (tid == 0) carry_s = 0;
    __syncthreads();
    for (int base = 0; base < N; base += 1024) {
        int i = base + tid;
        int v = (i < N) ? g_deg[i] : 0;
        int x = v;
#pragma unroll
        for (int o = 1; o < 32; o <<= 1) {
            int y = __shfl_up_sync(0xffffffffu, x, o);
            if (lane >= o) x += y;
        }
        if (lane == 31) wsum[wid] = x;
        __syncthreads();
        if (wid == 0) {
            int s = wsum[lane];
#pragma unroll
            for (int o = 1; o < 32; o <<= 1) {
                int y = __shfl_up_sync(0xffffffffu, s, o);
                if (lane >= o) s += y;
            }
            wsum[lane] = s;
        }
        __syncthreads();
        int incl  = x + (wid > 0 ? wsum[wid - 1] : 0);
        int total = wsum[31];
        int excl  = incl - v + carry_s;
        if (i < N) { g_off[i] = excl; g_cur[i] = excl; }
        __syncthreads();
        if (tid == 0) carry_s += total;
        __syncthreads();
    }
}

// ---------------- K5: CSR scatter + per-(edge,head) exp ---------------------
// softmax shift-invariance: alpha = exp(e)/sum(exp(e)); scores are O(1) so
// the max-subtraction pass is unnecessary.
__global__ void k_scatter(const int* __restrict__ EI,
                          const float* __restrict__ ba, int E) {
    int e = blockIdx.x * 256 + threadIdx.x;
    if (e >= E) return;
    int tgt = EI[e], src = EI[E + e];
    int pos = atomicAdd(&g_cur[tgt], 1);
    g_csrc[pos] = src;
    float4 si0 = *(const float4*)&g_si[tgt * HEADS];
    float4 si1 = *(const float4*)&g_si[tgt * HEADS + 4];
    float4 sj0 = *(const float4*)&g_sj[src * HEADS];
    float4 sj1 = *(const float4*)&g_sj[src * HEADS + 4];
    float sc[8] = { si0.x + sj0.x, si0.y + sj0.y, si0.z + sj0.z, si0.w + sj0.w,
                    si1.x + sj1.x, si1.y + sj1.y, si1.z + sj1.z, si1.w + sj1.w };
    float ex[8];
#pragma unroll
    for (int h = 0; h < 8; h++) {
        float s = sc[h] + ba[h];
        s = (s >= 0.f) ? s : SLOPE * s;
        ex[h] = __expf(s);
    }
    *(float4*)&g_ex[(size_t)pos * 8]     = *(float4*)&ex[0];
    *(float4*)&g_ex[(size_t)pos * 8 + 4] = *(float4*)&ex[4];
}

// ---------------- K6: gather-aggregate + skip + ELU + LN + head-mean --------
// block = node (256 threads), warp = head, lane = channel within head.
__global__ void __launch_bounds__(256)
k_agg(const float* __restrict__ gamma, const float* __restrict__ beta, int N) {
    int n = blockIdx.x;
    if (n >= N) return;
    const int tid  = threadIdx.x;
    const int h    = tid >> 5;
    const int lane = tid & 31;
    const int off  = g_off[n];
    const int deg  = g_deg[n];

    float acc = 0.f, den = 0.f;
#pragma unroll 4
    for (int k = 0; k < deg; k++) {
        int   src = __ldg(&g_csrc[off + k]);
        float ex  = __ldg(&g_ex[(size_t)(off + k) * 8 + h]);
        float hv  = __ldg(&g_H[(size_t)src * FDIM + h * HD + lane]);
        acc = fmaf(ex, hv, acc);
        den += ex;
    }
    float hval = g_H[(size_t)n * FDIM + tid];
    float v = (den > 0.f ? acc / den : 0.f) + hval;
    v = (v > 0.f) ? v : expm1f(v);
    float s = v, ss = v * v;
#pragma unroll
    for (int o = 16; o; o >>= 1) {
        s  += __shfl_xor_sync(0xffffffffu, s, o);
        ss += __shfl_xor_sync(0xffffffffu, ss, o);
    }
    float mu  = s * (1.f / HD);
    float var = ss * (1.f / HD) - mu * mu;
    float nrm = (v - mu) * rsqrtf(var + LN_EPS) * gamma[tid] + beta[tid];

    __shared__ float sm[FDIM];
    sm[tid] = nrm;
    __syncthreads();
    if (tid < HD) {
        float m = 0.f;
#pragma unroll
        for (int hh = 0; hh < HEADS; hh++) m += sm[hh * HD + tid];
        g_mean[(size_t)n * HD + tid] = m * (1.f / HEADS);
    }
}

// ---------------- K7: out = ELU(mean @ Wout + bout) -------------------------
__global__ void k_out(const float* __restrict__ Wout,
                      const float* __restrict__ bout,
                      float* __restrict__ out, int N) {
    __shared__ float sm[32][33];
    int row0 = blockIdx.x * 32;
    int tid  = threadIdx.x;
    for (int i = tid; i < 1024; i += 256) {
        int r = i >> 5, d = i & 31;
        sm[r][d] = (row0 + r < N) ? g_mean[(size_t)(row0 + r) * HD + d] : 0.f;
    }
    __syncthreads();
    int col = tid;
    float w[32];
#pragma unroll
    for (int d = 0; d < 32; d++) w[d] = Wout[d * FDIM + col];
    float b = bout[col];
    for (int r = 0; r < 32; r++) {
        if (row0 + r >= N) break;
        float acc = b;
#pragma unroll
        for (int d = 0; d < 32; d++) acc += sm[r][d] * w[d];
        acc = (acc > 0.f) ? acc : expm1f(acc);
        out[(size_t)(row0 + r) * FDIM + col] = acc;
    }
}

// ---------------- launch -----------------------------------------------------
extern "C" void kernel_launch(void* const* d_in, const int* in_sizes, int n_in,
                              void* d_out, int out_size) {
    const float* X    = (const float*)d_in[0];
    const int*   EI   = (const int*)  d_in[1];
    const float* W    = (const float*)d_in[2];
    const float* bw   = (const float*)d_in[3];
    const float* A    = (const float*)d_in[4];
    const float* ba   = (const float*)d_in[5];
    const float* gmm  = (const float*)d_in[6];
    const float* bet  = (const float*)d_in[7];
    const float* Wout = (const float*)d_in[8];
    const float* bout = (const float*)d_in[9];
    float* out = (float*)d_out;

    const int N = in_sizes[0] / FDIM;
    const int E = in_sizes[1] / 2;

    // CSR build (independent of GEMM)
    k_zero<<<(N + 255) / 256, 256>>>(N);
    k_hist<<<(E + 255) / 256, 256>>>(EI, E);
    k_scan<<<1, 1024>>>(N);

    // feature GEMM + attention pre-scores
    {
        dim3 grid(FDIM / 128, (N + 127) / 128);
        k_gemm_h<<<grid, 256>>>(X, W, bw, N);
    }
    k_scores<<<N, 256>>>(A, N);

    // CSR scatter with fused exp(score)
    k_scatter<<<(E + 255) / 256, 256>>>(EI, ba, E);

    // fused gather-aggregate + softmax-normalize + skip + ELU + LN + head mean
    k_agg<<<N, 256>>>(gmm, bet, N);

    // final projection + ELU
    k_out<<<(N + 31) / 32, 256>>>(Wout, bout, out, N);
}

// round 4
// speedup vs baseline: 1.6434x; 1.4495x over previous
#include <cuda_runtime.h>
#include <cuda_bf16.h>
#include <cstdint>

#define N_MAX    50000
#define E_MAX    1600000
#define HEADS    8
#define HD       32
#define FDIM     256          // HEADS*HD == F_IN == HID
#define SLOPE    0.2f
#define LN_EPS   1e-5f

// ---------------- scratch (device globals; no allocation allowed) ----------
__device__ float    g_H   [N_MAX * FDIM];   // h per node, [n][head*32+d]
__device__ float    g_si  [N_MAX * HEADS];
__device__ float    g_sj  [N_MAX * HEADS];
__device__ float    g_mean[N_MAX * HD];
__device__ int      g_deg [N_MAX];
__device__ int      g_off [N_MAX];
__device__ int      g_cur [N_MAX];
__device__ int      g_csrc[E_MAX];          // CSR: src per slot
__device__ float    g_ex  [E_MAX * HEADS];  // CSR-ordered exp(score) per head

// ---------------- K0: zero degree counters ---------------------------------
__global__ void k_zero(int N) {
    int i = blockIdx.x * 256 + threadIdx.x;
    if (i < N) g_deg[i] = 0;
}

__device__ __forceinline__ uint32_t f2tf32(float f) {
    uint32_t t;
    asm("cvt.rna.tf32.f32 %0, %1;" : "=r"(t) : "f"(f));
    return t;
}

// ---------------- K1: H = X @ Wf + bw  (tf32 tensor-core GEMM) --------------
// Block tile 128x128, BK=32, 8 warps (4 M x 2 N), warp tile 32x64.
// Wf[k][c] = W[(c>>5)*F_IN*HD + k*HD + (c&31)],  c = head*32 + d
__global__ void __launch_bounds__(256, 2)
k_gemm_h(const float* __restrict__ X, const float* __restrict__ W,
         const float* __restrict__ bw, int N) {
    __shared__ float As[128][36];   // [m][k], stride 36 -> bank 4r+c bijective
    __shared__ float Bs[32][136];   // [k][n], stride 136 -> bank 8c+r bijective

    const int tid  = threadIdx.x;
    const int wid  = tid >> 5, lane = tid & 31;
    const int wm   = (wid & 3) * 32;     // warp M offset in tile
    const int wn   = (wid >> 2) * 64;    // warp N offset
    const int r    = lane >> 2, c = lane & 3;
    const int row0 = blockIdx.y * 128;
    const int col0 = blockIdx.x * 128;

    float acc[2][8][4];
#pragma unroll
    for (int mf = 0; mf < 2; mf++)
#pragma unroll
        for (int nf = 0; nf < 8; nf++)
#pragma unroll
            for (int i = 0; i < 4; i++) acc[mf][nf][i] = 0.f;

    for (int k0 = 0; k0 < FDIM; k0 += 32) {
        // A tile: 128 rows x 32 k = 1024 float4
#pragma unroll
        for (int i = 0; i < 4; i++) {
            int v = tid + i * 256;
            int m = v >> 3, kq = (v & 7) * 4;
            float4 xv = make_float4(0.f, 0.f, 0.f, 0.f);
            if (row0 + m < N)
                xv = *(const float4*)&X[(size_t)(row0 + m) * FDIM + k0 + kq];
            uint4 tv = make_uint4(f2tf32(xv.x), f2tf32(xv.y),
                                  f2tf32(xv.z), f2tf32(xv.w));
            *(uint4*)&As[m][kq] = tv;
        }
        // B tile: 32 k x 128 n = 1024 float4
#pragma unroll
        for (int i = 0; i < 4; i++) {
            int v = tid + i * 256;
            int k = v >> 5, n4 = (v & 31) * 4;
            int cc = col0 + n4;
            float4 wv = *(const float4*)
                &W[(size_t)(cc >> 5) * FDIM * HD + (size_t)(k0 + k) * HD + (cc & 31)];
            uint4 tv = make_uint4(f2tf32(wv.x), f2tf32(wv.y),
                                  f2tf32(wv.z), f2tf32(wv.w));
            *(uint4*)&Bs[k][n4] = tv;
        }
        __syncthreads();
#pragma unroll
        for (int kc = 0; kc < 32; kc += 8) {
            uint32_t a[2][4], b[8][2];
#pragma unroll
            for (int mf = 0; mf < 2; mf++) {
                a[mf][0] = __float_as_uint(As[wm + mf * 16 + r    ][kc + c    ]);
                a[mf][1] = __float_as_uint(As[wm + mf * 16 + r + 8][kc + c    ]);
                a[mf][2] = __float_as_uint(As[wm + mf * 16 + r    ][kc + c + 4]);
                a[mf][3] = __float_as_uint(As[wm + mf * 16 + r + 8][kc + c + 4]);
            }
#pragma unroll
            for (int nf = 0; nf < 8; nf++) {
                b[nf][0] = __float_as_uint(Bs[kc + c    ][wn + nf * 8 + r]);
                b[nf][1] = __float_as_uint(Bs[kc + c + 4][wn + nf * 8 + r]);
            }
#pragma unroll
            for (int mf = 0; mf < 2; mf++)
#pragma unroll
                for (int nf = 0; nf < 8; nf++)
                    asm volatile(
                        "mma.sync.aligned.m16n8k8.row.col.f32.tf32.tf32.f32 "
                        "{%0,%1,%2,%3}, {%4,%5,%6,%7}, {%8,%9}, {%0,%1,%2,%3};"
                        : "+f"(acc[mf][nf][0]), "+f"(acc[mf][nf][1]),
                          "+f"(acc[mf][nf][2]), "+f"(acc[mf][nf][3])
                        : "r"(a[mf][0]), "r"(a[mf][1]),
                          "r"(a[mf][2]), "r"(a[mf][3]),
                          "r"(b[nf][0]), "r"(b[nf][1]));
        }
        __syncthreads();
    }
    // epilogue: + bw, store (c0,c1 -> row r; c2,c3 -> row r+8; cols 2c,2c+1)
#pragma unroll
    for (int mf = 0; mf < 2; mf++)
#pragma unroll
        for (int i = 0; i < 2; i++) {
            int row = row0 + wm + mf * 16 + r + i * 8;
            if (row < N) {
#pragma unroll
                for (int nf = 0; nf < 8; nf++) {
                    int cc = col0 + wn + nf * 8 + 2 * c;
                    float2 o;
                    o.x = acc[mf][nf][i * 2 + 0] + bw[cc];
                    o.y = acc[mf][nf][i * 2 + 1] + bw[cc + 1];
                    *(float2*)&g_H[(size_t)row * FDIM + cc] = o;
                }
            }
        }
}

// ---------------- K2: si/sj per (node, head) — warp per head ---------------
__global__ void k_scores(const float* __restrict__ A, int N) {
    int n = blockIdx.x;
    if (n >= N) return;
    int h    = threadIdx.x >> 5;
    int lane = threadIdx.x & 31;
    float x  = g_H[(size_t)n * FDIM + h * HD + lane];
    float s1 = x * A[h * 2 * HD + lane];
    float s2 = x * A[h * 2 * HD + HD + lane];
#pragma unroll
    for (int o = 16; o; o >>= 1) {
        s1 += __shfl_xor_sync(0xffffffffu, s1, o);
        s2 += __shfl_xor_sync(0xffffffffu, s2, o);
    }
    if (lane == 0) {
        g_si[n * HEADS + h] = s1;
        g_sj[n * HEADS + h] = s2;
    }
}

// ---------------- K3: degree histogram --------------------------------------
__global__ void k_hist(const int* __restrict__ EI, int E) {
    int e = blockIdx.x * 256 + threadIdx.x;
    if (e < E) atomicAdd(&g_deg[EI[e]], 1);
}

// ---------------- K4: exclusive scan (single block, 1024 threads) -----------
__global__ void __launch_bounds__(1024)
k_scan(int N) {
    __shared__ int wsum[32];
    __shared__ int carry_s;
    int tid = threadIdx.x, lane = tid & 31, wid = tid >> 5;
    if (tid == 0) carry_s = 0;
    __syncthreads();
    for (int base = 0; base < N; base += 1024) {
        int i = base + tid;
        int v = (i < N) ? g_deg[i] : 0;
        int x = v;
#pragma unroll
        for (int o = 1; o < 32; o <<= 1) {
            int y = __shfl_up_sync(0xffffffffu, x, o);
            if (lane >= o) x += y;
        }
        if (lane == 31) wsum[wid] = x;
        __syncthreads();
        if (wid == 0) {
            int s = wsum[lane];
#pragma unroll
            for (int o = 1; o < 32; o <<= 1) {
                int y = __shfl_up_sync(0xffffffffu, s, o);
                if (lane >= o) s += y;
            }
            wsum[lane] = s;
        }
        __syncthreads();
        int incl  = x + (wid > 0 ? wsum[wid - 1] : 0);
        int total = wsum[31];
        int excl  = incl - v + carry_s;
        if (i < N) { g_off[i] = excl; g_cur[i] = excl; }
        __syncthreads();
        if (tid == 0) carry_s += total;
        __syncthreads();
    }
}

// ---------------- K5: CSR scatter + per-(edge,head) exp ---------------------
__global__ void k_scatter(const int* __restrict__ EI,
                          const float* __restrict__ ba, int E) {
    int e = blockIdx.x * 256 + threadIdx.x;
    if (e >= E) return;
    int tgt = EI[e], src = EI[E + e];
    int pos = atomicAdd(&g_cur[tgt], 1);
    g_csrc[pos] = src;
    float4 si0 = *(const float4*)&g_si[tgt * HEADS];
    float4 si1 = *(const float4*)&g_si[tgt * HEADS + 4];
    float4 sj0 = *(const float4*)&g_sj[src * HEADS];
    float4 sj1 = *(const float4*)&g_sj[src * HEADS + 4];
    float sc[8] = { si0.x + sj0.x, si0.y + sj0.y, si0.z + sj0.z, si0.w + sj0.w,
                    si1.x + sj1.x, si1.y + sj1.y, si1.z + sj1.z, si1.w + sj1.w };
    float ex[8];
#pragma unroll
    for (int h = 0; h < 8; h++) {
        float s = sc[h] + ba[h];
        s = (s >= 0.f) ? s : SLOPE * s;
        ex[h] = __expf(s);
    }
    *(float4*)&g_ex[(size_t)pos * 8]     = *(float4*)&ex[0];
    *(float4*)&g_ex[(size_t)pos * 8 + 4] = *(float4*)&ex[4];
}

// ---------------- K6: gather-aggregate + skip + ELU + LN + head-mean --------
// block = node; 8 warps split the edge list; each warp covers ALL 256
// channels per edge via 2x float4 loads; ex broadcast via shfl.
__global__ void __launch_bounds__(256)
k_agg(const float* __restrict__ gamma, const float* __restrict__ beta, int N) {
    int n = blockIdx.x;
    if (n >= N) return;
    const int tid  = threadIdx.x;
    const int wid  = tid >> 5;
    const int lane = tid & 31;
    const int h0   = lane >> 3;          // head of v0 channels (0..3)
    const int off  = g_off[n];
    const int deg  = g_deg[n];

    float4 acc0 = make_float4(0.f, 0.f, 0.f, 0.f);
    float4 acc1 = make_float4(0.f, 0.f, 0.f, 0.f);
    float den0 = 0.f, den1 = 0.f;

#pragma unroll 2
    for (int k = wid; k < deg; k += 8) {
        int   slot = off + k;
        int   src  = __ldg(&g_csrc[slot]);
        float exv  = (lane < 8) ? __ldg(&g_ex[(size_t)slot * 8 + lane]) : 0.f;
        float a0 = __shfl_sync(0xffffffffu, exv, h0);
        float a1 = __shfl_sync(0xffffffffu, exv, h0 + 4);
        const float4* hs = (const float4*)&g_H[(size_t)src * FDIM];
        float4 v0 = __ldg(&hs[lane]);       // channels 4*lane..+3     (head h0)
        float4 v1 = __ldg(&hs[32 + lane]);  // channels 128+4*lane..+3 (head h0+4)
        acc0.x = fmaf(a0, v0.x, acc0.x); acc0.y = fmaf(a0, v0.y, acc0.y);
        acc0.z = fmaf(a0, v0.z, acc0.z); acc0.w = fmaf(a0, v0.w, acc0.w);
        acc1.x = fmaf(a1, v1.x, acc1.x); acc1.y = fmaf(a1, v1.y, acc1.y);
        acc1.z = fmaf(a1, v1.z, acc1.z); acc1.w = fmaf(a1, v1.w, acc1.w);
        den0 += a0; den1 += a1;
    }

    __shared__ float sacc[8][FDIM];
    __shared__ float sden[8][HEADS];
    *(float4*)&sacc[wid][lane * 4]       = acc0;
    *(float4*)&sacc[wid][128 + lane * 4] = acc1;
    if ((lane & 7) == 0) {
        sden[wid][h0]     = den0;
        sden[wid][h0 + 4] = den1;
    }
    __syncthreads();

    // channel c = tid; reduce partials
    float acc = 0.f, den = 0.f;
#pragma unroll
    for (int w = 0; w < 8; w++) {
        acc += sacc[w][tid];
        den += sden[w][tid >> 5];
    }
    float hval = g_H[(size_t)n * FDIM + tid];
    float v = (den > 0.f ? acc / den : 0.f) + hval;
    v = (v > 0.f) ? v : expm1f(v);
    float s = v, ss = v * v;
#pragma unroll
    for (int o = 16; o; o >>= 1) {
        s  += __shfl_xor_sync(0xffffffffu, s, o);
        ss += __shfl_xor_sync(0xffffffffu, ss, o);
    }
    float mu  = s * (1.f / HD);
    float var = ss * (1.f / HD) - mu * mu;
    float nrm = (v - mu) * rsqrtf(var + LN_EPS) * gamma[tid] + beta[tid];

    __shared__ float smn[FDIM];
    smn[tid] = nrm;
    __syncthreads();
    if (tid < HD) {
        float m = 0.f;
#pragma unroll
        for (int hh = 0; hh < HEADS; hh++) m += smn[hh * HD + tid];
        g_mean[(size_t)n * HD + tid] = m * (1.f / HEADS);
    }
}

// ---------------- K7: out = ELU(mean @ Wout + bout) -------------------------
__global__ void k_out(const float* __restrict__ Wout,
                      const float* __restrict__ bout,
                      float* __restrict__ out, int N) {
    __shared__ float sm[32][33];
    int row0 = blockIdx.x * 32;
    int tid  = threadIdx.x;
    for (int i = tid; i < 1024; i += 256) {
        int r = i >> 5, d = i & 31;
        sm[r][d] = (row0 + r < N) ? g_mean[(size_t)(row0 + r) * HD + d] : 0.f;
    }
    __syncthreads();
    int col = tid;
    float w[32];
#pragma unroll
    for (int d = 0; d < 32; d++) w[d] = Wout[d * FDIM + col];
    float b = bout[col];
    for (int r = 0; r < 32; r++) {
        if (row0 + r >= N) break;
        float acc = b;
#pragma unroll
        for (int d = 0; d < 32; d++) acc += sm[r][d] * w[d];
        acc = (acc > 0.f) ? acc : expm1f(acc);
        out[(size_t)(row0 + r) * FDIM + col] = acc;
    }
}

// ---------------- launch -----------------------------------------------------
extern "C" void kernel_launch(void* const* d_in, const int* in_sizes, int n_in,
                              void* d_out, int out_size) {
    const float* X    = (const float*)d_in[0];
    const int*   EI   = (const int*)  d_in[1];
    const float* W    = (const float*)d_in[2];
    const float* bw   = (const float*)d_in[3];
    const float* A    = (const float*)d_in[4];
    const float* ba   = (const float*)d_in[5];
    const float* gmm  = (const float*)d_in[6];
    const float* bet  = (const float*)d_in[7];
    const float* Wout = (const float*)d_in[8];
    const float* bout = (const float*)d_in[9];
    float* out = (float*)d_out;

    const int N = in_sizes[0] / FDIM;
    const int E = in_sizes[1] / 2;

    // CSR build (independent of GEMM)
    k_zero<<<(N + 255) / 256, 256>>>(N);
    k_hist<<<(E + 255) / 256, 256>>>(EI, E);
    k_scan<<<1, 1024>>>(N);

    // feature GEMM (tf32 tensor cores) + attention pre-scores
    {
        dim3 grid(FDIM / 128, (N + 127) / 128);
        k_gemm_h<<<grid, 256>>>(X, W, bw, N);
    }
    k_scores<<<N, 256>>>(A, N);

    // CSR scatter with fused exp(score)
    k_scatter<<<(E + 255) / 256, 256>>>(EI, ba, E);

    // fused gather-aggregate + softmax-normalize + skip + ELU + LN + head mean
    k_agg<<<N, 256>>>(gmm, bet, N);

    // final projection + ELU
    k_out<<<(N + 31) / 32, 256>>>(Wout, bout, out, N);
}

// round 5
// speedup vs baseline: 1.8492x; 1.1252x over previous
#include <cuda_runtime.h>
#include <cuda_bf16.h>
#include <cstdint>

#define N_MAX    50000
#define E_MAX    1600000
#define HEADS    8
#define HD       32
#define FDIM     256          // HEADS*HD == F_IN == HID
#define SLOPE    0.2f
#define LN_EPS   1e-5f
#define SCAN_T   1024

// ---------------- scratch (device globals; no allocation allowed) ----------
__device__ float    g_H   [N_MAX * FDIM];   // h per node, [n][head*32+d]
__device__ float    g_si  [N_MAX * HEADS];
__device__ float    g_sj  [N_MAX * HEADS];
__device__ float    g_mean[N_MAX * HD];
__device__ int      g_deg [N_MAX];
__device__ int      g_off [N_MAX];
__device__ int      g_cur [N_MAX];
__device__ int      g_bsum[1024];
__device__ int      g_csrc[E_MAX];          // CSR: src per slot

// ---------------- K0: zero degree counters ---------------------------------
__global__ void k_zero(int N) {
    int i = blockIdx.x * 256 + threadIdx.x;
    if (i < N) g_deg[i] = 0;
}

__device__ __forceinline__ uint32_t f2tf32(float f) {
    uint32_t t;
    asm("cvt.rna.tf32.f32 %0, %1;" : "=r"(t) : "f"(f));
    return t;
}

// ---------------- K1: H = X @ Wf + bw  (tf32 tensor-core GEMM) --------------
__global__ void __launch_bounds__(256, 2)
k_gemm_h(const float* __restrict__ X, const float* __restrict__ W,
         const float* __restrict__ bw, int N) {
    __shared__ float As[128][36];
    __shared__ float Bs[32][136];

    const int tid  = threadIdx.x;
    const int wid  = tid >> 5, lane = tid & 31;
    const int wm   = (wid & 3) * 32;
    const int wn   = (wid >> 2) * 64;
    const int r    = lane >> 2, c = lane & 3;
    const int row0 = blockIdx.y * 128;
    const int col0 = blockIdx.x * 128;

    float acc[2][8][4];
#pragma unroll
    for (int mf = 0; mf < 2; mf++)
#pragma unroll
        for (int nf = 0; nf < 8; nf++)
#pragma unroll
            for (int i = 0; i < 4; i++) acc[mf][nf][i] = 0.f;

    for (int k0 = 0; k0 < FDIM; k0 += 32) {
#pragma unroll
        for (int i = 0; i < 4; i++) {
            int v = tid + i * 256;
            int m = v >> 3, kq = (v & 7) * 4;
            float4 xv = make_float4(0.f, 0.f, 0.f, 0.f);
            if (row0 + m < N)
                xv = *(const float4*)&X[(size_t)(row0 + m) * FDIM + k0 + kq];
            uint4 tv = make_uint4(f2tf32(xv.x), f2tf32(xv.y),
                                  f2tf32(xv.z), f2tf32(xv.w));
            *(uint4*)&As[m][kq] = tv;
        }
#pragma unroll
        for (int i = 0; i < 4; i++) {
            int v = tid + i * 256;
            int k = v >> 5, n4 = (v & 31) * 4;
            int cc = col0 + n4;
            float4 wv = *(const float4*)
                &W[(size_t)(cc >> 5) * FDIM * HD + (size_t)(k0 + k) * HD + (cc & 31)];
            uint4 tv = make_uint4(f2tf32(wv.x), f2tf32(wv.y),
                                  f2tf32(wv.z), f2tf32(wv.w));
            *(uint4*)&Bs[k][n4] = tv;
        }
        __syncthreads();
#pragma unroll
        for (int kc = 0; kc < 32; kc += 8) {
            uint32_t a[2][4], b[8][2];
#pragma unroll
            for (int mf = 0; mf < 2; mf++) {
                a[mf][0] = __float_as_uint(As[wm + mf * 16 + r    ][kc + c    ]);
                a[mf][1] = __float_as_uint(As[wm + mf * 16 + r + 8][kc + c    ]);
                a[mf][2] = __float_as_uint(As[wm + mf * 16 + r    ][kc + c + 4]);
                a[mf][3] = __float_as_uint(As[wm + mf * 16 + r + 8][kc + c + 4]);
            }
#pragma unroll
            for (int nf = 0; nf < 8; nf++) {
                b[nf][0] = __float_as_uint(Bs[kc + c    ][wn + nf * 8 + r]);
                b[nf][1] = __float_as_uint(Bs[kc + c + 4][wn + nf * 8 + r]);
            }
#pragma unroll
            for (int mf = 0; mf < 2; mf++)
#pragma unroll
                for (int nf = 0; nf < 8; nf++)
                    asm volatile(
                        "mma.sync.aligned.m16n8k8.row.col.f32.tf32.tf32.f32 "
                        "{%0,%1,%2,%3}, {%4,%5,%6,%7}, {%8,%9}, {%0,%1,%2,%3};"
                        : "+f"(acc[mf][nf][0]), "+f"(acc[mf][nf][1]),
                          "+f"(acc[mf][nf][2]), "+f"(acc[mf][nf][3])
                        : "r"(a[mf][0]), "r"(a[mf][1]),
                          "r"(a[mf][2]), "r"(a[mf][3]),
                          "r"(b[nf][0]), "r"(b[nf][1]));
        }
        __syncthreads();
    }
#pragma unroll
    for (int mf = 0; mf < 2; mf++)
#pragma unroll
        for (int i = 0; i < 2; i++) {
            int row = row0 + wm + mf * 16 + r + i * 8;
            if (row < N) {
#pragma unroll
                for (int nf = 0; nf < 8; nf++) {
                    int cc = col0 + wn + nf * 8 + 2 * c;
                    float2 o;
                    o.x = acc[mf][nf][i * 2 + 0] + bw[cc];
                    o.y = acc[mf][nf][i * 2 + 1] + bw[cc + 1];
                    *(float2*)&g_H[(size_t)row * FDIM + cc] = o;
                }
            }
        }
}

// ---------------- K2: si/sj per (node, head) — warp per head ---------------
__global__ void k_scores(const float* __restrict__ A, int N) {
    int n = blockIdx.x;
    if (n >= N) return;
    int h    = threadIdx.x >> 5;
    int lane = threadIdx.x & 31;
    float x  = g_H[(size_t)n * FDIM + h * HD + lane];
    float s1 = x * A[h * 2 * HD + lane];
    float s2 = x * A[h * 2 * HD + HD + lane];
#pragma unroll
    for (int o = 16; o; o >>= 1) {
        s1 += __shfl_xor_sync(0xffffffffu, s1, o);
        s2 += __shfl_xor_sync(0xffffffffu, s2, o);
    }
    if (lane == 0) {
        g_si[n * HEADS + h] = s1;
        g_sj[n * HEADS + h] = s2;
    }
}

// ---------------- K3: degree histogram --------------------------------------
__global__ void k_hist(const int* __restrict__ EI, int E) {
    int e = blockIdx.x * 256 + threadIdx.x;
    if (e < E) atomicAdd(&g_deg[EI[e]], 1);
}

// ---------------- K4a: per-tile totals --------------------------------------
__global__ void __launch_bounds__(SCAN_T)
k_scan1(int N) {
    __shared__ int ws[32];
    int tid = threadIdx.x, lane = tid & 31, wid = tid >> 5;
    int i = blockIdx.x * SCAN_T + tid;
    int v = (i < N) ? g_deg[i] : 0;
#pragma unroll
    for (int o = 16; o; o >>= 1) v += __shfl_xor_sync(0xffffffffu, v, o);
    if (lane == 0) ws[wid] = v;
    __syncthreads();
    if (wid == 0) {
        int s = ws[lane];
#pragma unroll
        for (int o = 16; o; o >>= 1) s += __shfl_xor_sync(0xffffffffu, s, o);
        if (lane == 0) g_bsum[blockIdx.x] = s;
    }
}

// ---------------- K4b: scan tile totals (1 small block) ---------------------
__global__ void __launch_bounds__(SCAN_T)
k_scan2(int nb) {
    __shared__ int ws[32];
    int tid = threadIdx.x, lane = tid & 31, wid = tid >> 5;
    int v = (tid < nb) ? g_bsum[tid] : 0;
    int x = v;
#pragma unroll
    for (int o = 1; o < 32; o <<= 1) {
        int y = __shfl_up_sync(0xffffffffu, x, o);
        if (lane >= o) x += y;
    }
    if (lane == 31) ws[wid] = x;
    __syncthreads();
    if (wid == 0) {
        int s = ws[lane];
#pragma unroll
        for (int o = 1; o < 32; o <<= 1) {
            int y = __shfl_up_sync(0xffffffffu, s, o);
            if (lane >= o) s += y;
        }
        ws[lane] = s;
    }
    __syncthreads();
    int excl = x - v + (wid > 0 ? ws[wid - 1] : 0);
    if (tid < nb) g_bsum[tid] = excl;
}

// ---------------- K4c: intra-tile scan + global offset ----------------------
__global__ void __launch_bounds__(SCAN_T)
k_scan3(int N) {
    __shared__ int ws[32];
    int tid = threadIdx.x, lane = tid & 31, wid = tid >> 5;
    int i = blockIdx.x * SCAN_T + tid;
    int v = (i < N) ? g_deg[i] : 0;
    int x = v;
#pragma unroll
    for (int o = 1; o < 32; o <<= 1) {
        int y = __shfl_up_sync(0xffffffffu, x, o);
        if (lane >= o) x += y;
    }
    if (lane == 31) ws[wid] = x;
    __syncthreads();
    if (wid == 0) {
        int s = ws[lane];
#pragma unroll
        for (int o = 1; o < 32; o <<= 1) {
            int y = __shfl_up_sync(0xffffffffu, s, o);
            if (lane >= o) s += y;
        }
        ws[lane] = s;
    }
    __syncthreads();
    int excl = x - v + (wid > 0 ? ws[wid - 1] : 0) + g_bsum[blockIdx.x];
    if (i < N) { g_off[i] = excl; g_cur[i] = excl; }
}

// ---------------- K5: CSR scatter (src only; exp computed in k_agg) ---------
__global__ void k_scatter(const int* __restrict__ EI, int E) {
    int e = blockIdx.x * 256 + threadIdx.x;
    if (e >= E) return;
    int tgt = EI[e], src = EI[E + e];
    int pos = atomicAdd(&g_cur[tgt], 1);
    g_csrc[pos] = src;
}

// ---------------- K6: gather-aggregate + softmax + skip + ELU + LN + mean ---
// block = node; 8 warps split the edge list; each warp covers ALL 256
// channels per edge; exp(score) computed on the fly by lanes 0-7.
__global__ void __launch_bounds__(256)
k_agg(const float* __restrict__ gamma, const float* __restrict__ beta,
      const float* __restrict__ ba, int N) {
    int n = blockIdx.x;
    if (n >= N) return;
    const int tid  = threadIdx.x;
    const int wid  = tid >> 5;
    const int lane = tid & 31;
    const int h0   = lane >> 3;          // head of v0 channels (0..3)

    __shared__ float s_sib[HEADS];       // si[n][h] + ba[h]
    if (tid < HEADS) s_sib[tid] = g_si[n * HEADS + tid] + ba[tid];
    const int off = g_off[n];
    const int deg = g_deg[n];
    __syncthreads();
    const float sib = (lane < 8) ? s_sib[lane] : 0.f;

    float4 acc0 = make_float4(0.f, 0.f, 0.f, 0.f);
    float4 acc1 = make_float4(0.f, 0.f, 0.f, 0.f);
    float den0 = 0.f, den1 = 0.f;

#pragma unroll 4
    for (int k = wid; k < deg; k += 8) {
        int   slot = off + k;
        int   src  = __ldg(&g_csrc[slot]);
        float exv  = 0.f;
        if (lane < 8) {
            float s = sib + __ldg(&g_sj[src * HEADS + lane]);
            s = (s >= 0.f) ? s : SLOPE * s;
            exv = __expf(s);
        }
        float a0 = __shfl_sync(0xffffffffu, exv, h0);
        float a1 = __shfl_sync(0xffffffffu, exv, h0 + 4);
        const float4* hs = (const float4*)&g_H[(size_t)src * FDIM];
        float4 v0 = __ldg(&hs[lane]);
        float4 v1 = __ldg(&hs[32 + lane]);
        acc0.x = fmaf(a0, v0.x, acc0.x); acc0.y = fmaf(a0, v0.y, acc0.y);
        acc0.z = fmaf(a0, v0.z, acc0.z); acc0.w = fmaf(a0, v0.w, acc0.w);
        acc1.x = fmaf(a1, v1.x, acc1.x); acc1.y = fmaf(a1, v1.y, acc1.y);
        acc1.z = fmaf(a1, v1.z, acc1.z); acc1.w = fmaf(a1, v1.w, acc1.w);
        den0 += a0; den1 += a1;
    }

    __shared__ float sacc[8][FDIM];
    __shared__ float sden[8][HEADS];
    *(float4*)&sacc[wid][lane * 4]       = acc0;
    *(float4*)&sacc[wid][128 + lane * 4] = acc1;
    if ((lane & 7) == 0) {
        sden[wid][h0]     = den0;
        sden[wid][h0 + 4] = den1;
    }
    __syncthreads();

    float acc = 0.f, den = 0.f;
#pragma unroll
    for (int w = 0; w < 8; w++) {
        acc += sacc[w][tid];
        den += sden[w][tid >> 5];
    }
    float hval = g_H[(size_t)n * FDIM + tid];
    float v = (den > 0.f ? acc / den : 0.f) + hval;
    v = (v > 0.f) ? v : expm1f(v);
    float s = v, ss = v * v;
#pragma unroll
    for (int o = 16; o; o >>= 1) {
        s  += __shfl_xor_sync(0xffffffffu, s, o);
        ss += __shfl_xor_sync(0xffffffffu, ss, o);
    }
    float mu  = s * (1.f / HD);
    float var = ss * (1.f / HD) - mu * mu;
    float nrm = (v - mu) * rsqrtf(var + LN_EPS) * gamma[tid] + beta[tid];

    __shared__ float smn[FDIM];
    smn[tid] = nrm;
    __syncthreads();
    if (tid < HD) {
        float m = 0.f;
#pragma unroll
        for (int hh = 0; hh < HEADS; hh++) m += smn[hh * HD + tid];
        g_mean[(size_t)n * HD + tid] = m * (1.f / HEADS);
    }
}

// ---------------- K7: out = ELU(mean @ Wout + bout) -------------------------
__global__ void k_out(const float* __restrict__ Wout,
                      const float* __restrict__ bout,
                      float* __restrict__ out, int N) {
    __shared__ float sm[32][33];
    int row0 = blockIdx.x * 32;
    int tid  = threadIdx.x;
    for (int i = tid; i < 1024; i += 256) {
        int r = i >> 5, d = i & 31;
        sm[r][d] = (row0 + r < N) ? g_mean[(size_t)(row0 + r) * HD + d] : 0.f;
    }
    __syncthreads();
    int col = tid;
    float w[32];
#pragma unroll
    for (int d = 0; d < 32; d++) w[d] = Wout[d * FDIM + col];
    float b = bout[col];
    for (int r = 0; r < 32; r++) {
        if (row0 + r >= N) break;
        float acc = b;
#pragma unroll
        for (int d = 0; d < 32; d++) acc += sm[r][d] * w[d];
        acc = (acc > 0.f) ? acc : expm1f(acc);
        out[(size_t)(row0 + r) * FDIM + col] = acc;
    }
}

// ---------------- launch -----------------------------------------------------
extern "C" void kernel_launch(void* const* d_in, const int* in_sizes, int n_in,
                              void* d_out, int out_size) {
    const float* X    = (const float*)d_in[0];
    const int*   EI   = (const int*)  d_in[1];
    const float* W    = (const float*)d_in[2];
    const float* bw   = (const float*)d_in[3];
    const float* A    = (const float*)d_in[4];
    const float* ba   = (const float*)d_in[5];
    const float* gmm  = (const float*)d_in[6];
    const float* bet  = (const float*)d_in[7];
    const float* Wout = (const float*)d_in[8];
    const float* bout = (const float*)d_in[9];
    float* out = (float*)d_out;

    const int N = in_sizes[0] / FDIM;
    const int E = in_sizes[1] / 2;
    const int nb = (N + SCAN_T - 1) / SCAN_T;

    // CSR build (independent of GEMM)
    k_zero<<<(N + 255) / 256, 256>>>(N);
    k_hist<<<(E + 255) / 256, 256>>>(EI, E);
    k_scan1<<<nb, SCAN_T>>>(N);
    k_scan2<<<1, SCAN_T>>>(nb);
    k_scan3<<<nb, SCAN_T>>>(N);
    k_scatter<<<(E + 255) / 256, 256>>>(EI, E);

    // feature GEMM (tf32 tensor cores) + attention pre-scores
    {
        dim3 grid(FDIM / 128, (N + 127) / 128);
        k_gemm_h<<<grid, 256>>>(X, W, bw, N);
    }
    k_scores<<<N, 256>>>(A, N);

    // fused gather-aggregate + softmax + skip + ELU + LN + head mean
    k_agg<<<N, 256>>>(gmm, bet, ba, N);

    // final projection + ELU
    k_out<<<(N + 31) / 32, 256>>>(Wout, bout, out, N);
}

// round 6
// speedup vs baseline: 2.0432x; 1.1049x over previous
#include <cuda_runtime.h>
#include <cuda_bf16.h>
#include <cuda_fp16.h>
#include <cstdint>

#define N_MAX    50000
#define E_MAX    1600000
#define HEADS    8
#define HD       32
#define FDIM     256          // HEADS*HD == F_IN == HID
#define SLOPE    0.2f
#define LN_EPS   1e-5f
#define SCAN_T   1024

// ---------------- scratch (device globals; no allocation allowed) ----------
__device__ float    g_H   [N_MAX * FDIM];   // h per node (fp32: skip/LN path)
__device__ __half   g_Hh  [N_MAX * FDIM];   // h per node (fp16: gather path)
__device__ float    g_si  [N_MAX * HEADS];
__device__ float    g_sj  [N_MAX * HEADS];
__device__ float    g_mean[N_MAX * HD];
__device__ int      g_deg [N_MAX];
__device__ int      g_off [N_MAX];
__device__ int      g_cur [N_MAX];
__device__ int      g_bsum[1024];
__device__ int      g_csrc[E_MAX];          // CSR: src per slot

// ---------------- K0: zero degree counters ---------------------------------
__global__ void k_zero(int N) {
    int i = blockIdx.x * 256 + threadIdx.x;
    if (i < N) g_deg[i] = 0;
}

__device__ __forceinline__ uint32_t f2tf32(float f) {
    uint32_t t;
    asm("cvt.rna.tf32.f32 %0, %1;" : "=r"(t) : "f"(f));
    return t;
}

// ---------------- K1: H = X @ Wf + bw  (tf32 tensor-core GEMM) --------------
__global__ void __launch_bounds__(256, 2)
k_gemm_h(const float* __restrict__ X, const float* __restrict__ W,
         const float* __restrict__ bw, int N) {
    __shared__ float As[128][36];
    __shared__ float Bs[32][136];

    const int tid  = threadIdx.x;
    const int wid  = tid >> 5, lane = tid & 31;
    const int wm   = (wid & 3) * 32;
    const int wn   = (wid >> 2) * 64;
    const int r    = lane >> 2, c = lane & 3;
    const int row0 = blockIdx.y * 128;
    const int col0 = blockIdx.x * 128;

    float acc[2][8][4];
#pragma unroll
    for (int mf = 0; mf < 2; mf++)
#pragma unroll
        for (int nf = 0; nf < 8; nf++)
#pragma unroll
            for (int i = 0; i < 4; i++) acc[mf][nf][i] = 0.f;

    for (int k0 = 0; k0 < FDIM; k0 += 32) {
#pragma unroll
        for (int i = 0; i < 4; i++) {
            int v = tid + i * 256;
            int m = v >> 3, kq = (v & 7) * 4;
            float4 xv = make_float4(0.f, 0.f, 0.f, 0.f);
            if (row0 + m < N)
                xv = *(const float4*)&X[(size_t)(row0 + m) * FDIM + k0 + kq];
            uint4 tv = make_uint4(f2tf32(xv.x), f2tf32(xv.y),
                                  f2tf32(xv.z), f2tf32(xv.w));
            *(uint4*)&As[m][kq] = tv;
        }
#pragma unroll
        for (int i = 0; i < 4; i++) {
            int v = tid + i * 256;
            int k = v >> 5, n4 = (v & 31) * 4;
            int cc = col0 + n4;
            float4 wv = *(const float4*)
                &W[(size_t)(cc >> 5) * FDIM * HD + (size_t)(k0 + k) * HD + (cc & 31)];
            uint4 tv = make_uint4(f2tf32(wv.x), f2tf32(wv.y),
                                  f2tf32(wv.z), f2tf32(wv.w));
            *(uint4*)&Bs[k][n4] = tv;
        }
        __syncthreads();
#pragma unroll
        for (int kc = 0; kc < 32; kc += 8) {
            uint32_t a[2][4], b[8][2];
#pragma unroll
            for (int mf = 0; mf < 2; mf++) {
                a[mf][0] = __float_as_uint(As[wm + mf * 16 + r    ][kc + c    ]);
                a[mf][1] = __float_as_uint(As[wm + mf * 16 + r + 8][kc + c    ]);
                a[mf][2] = __float_as_uint(As[wm + mf * 16 + r    ][kc + c + 4]);
                a[mf][3] = __float_as_uint(As[wm + mf * 16 + r + 8][kc + c + 4]);
            }
#pragma unroll
            for (int nf = 0; nf < 8; nf++) {
                b[nf][0] = __float_as_uint(Bs[kc + c    ][wn + nf * 8 + r]);
                b[nf][1] = __float_as_uint(Bs[kc + c + 4][wn + nf * 8 + r]);
            }
#pragma unroll
            for (int mf = 0; mf < 2; mf++)
#pragma unroll
                for (int nf = 0; nf < 8; nf++)
                    asm volatile(
                        "mma.sync.aligned.m16n8k8.row.col.f32.tf32.tf32.f32 "
                        "{%0,%1,%2,%3}, {%4,%5,%6,%7}, {%8,%9}, {%0,%1,%2,%3};"
                        : "+f"(acc[mf][nf][0]), "+f"(acc[mf][nf][1]),
                          "+f"(acc[mf][nf][2]), "+f"(acc[mf][nf][3])
                        : "r"(a[mf][0]), "r"(a[mf][1]),
                          "r"(a[mf][2]), "r"(a[mf][3]),
                          "r"(b[nf][0]), "r"(b[nf][1]));
        }
        __syncthreads();
    }
#pragma unroll
    for (int mf = 0; mf < 2; mf++)
#pragma unroll
        for (int i = 0; i < 2; i++) {
            int row = row0 + wm + mf * 16 + r + i * 8;
            if (row < N) {
#pragma unroll
                for (int nf = 0; nf < 8; nf++) {
                    int cc = col0 + wn + nf * 8 + 2 * c;
                    float2 o;
                    o.x = acc[mf][nf][i * 2 + 0] + bw[cc];
                    o.y = acc[mf][nf][i * 2 + 1] + bw[cc + 1];
                    *(float2*)&g_H[(size_t)row * FDIM + cc] = o;
                    *(__half2*)&g_Hh[(size_t)row * FDIM + cc] =
                        __floats2half2_rn(o.x, o.y);
                }
            }
        }
}

// ---------------- K2: si/sj per (node, head) — warp per head ---------------
__global__ void k_scores(const float* __restrict__ A, int N) {
    int n = blockIdx.x;
    if (n >= N) return;
    int h    = threadIdx.x >> 5;
    int lane = threadIdx.x & 31;
    float x  = g_H[(size_t)n * FDIM + h * HD + lane];
    float s1 = x * A[h * 2 * HD + lane];
    float s2 = x * A[h * 2 * HD + HD + lane];
#pragma unroll
    for (int o = 16; o; o >>= 1) {
        s1 += __shfl_xor_sync(0xffffffffu, s1, o);
        s2 += __shfl_xor_sync(0xffffffffu, s2, o);
    }
    if (lane == 0) {
        g_si[n * HEADS + h] = s1;
        g_sj[n * HEADS + h] = s2;
    }
}

// ---------------- K3: degree histogram --------------------------------------
__global__ void k_hist(const int* __restrict__ EI, int E) {
    int e = blockIdx.x * 256 + threadIdx.x;
    if (e < E) atomicAdd(&g_deg[EI[e]], 1);
}

// ---------------- K4a: per-tile totals --------------------------------------
__global__ void __launch_bounds__(SCAN_T)
k_scan1(int N) {
    __shared__ int ws[32];
    int tid = threadIdx.x, lane = tid & 31, wid = tid >> 5;
    int i = blockIdx.x * SCAN_T + tid;
    int v = (i < N) ? g_deg[i] : 0;
#pragma unroll
    for (int o = 16; o; o >>= 1) v += __shfl_xor_sync(0xffffffffu, v, o);
    if (lane == 0) ws[wid] = v;
    __syncthreads();
    if (wid == 0) {
        int s = ws[lane];
#pragma unroll
        for (int o = 16; o; o >>= 1) s += __shfl_xor_sync(0xffffffffu, s, o);
        if (lane == 0) g_bsum[blockIdx.x] = s;
    }
}

// ---------------- K4b: scan tile totals (1 small block) ---------------------
__global__ void __launch_bounds__(SCAN_T)
k_scan2(int nb) {
    __shared__ int ws[32];
    int tid = threadIdx.x, lane = tid & 31, wid = tid >> 5;
    int v = (tid < nb) ? g_bsum[tid] : 0;
    int x = v;
#pragma unroll
    for (int o = 1; o < 32; o <<= 1) {
        int y = __shfl_up_sync(0xffffffffu, x, o);
        if (lane >= o) x += y;
    }
    if (lane == 31) ws[wid] = x;
    __syncthreads();
    if (wid == 0) {
        int s = ws[lane];
#pragma unroll
        for (int o = 1; o < 32; o <<= 1) {
            int y = __shfl_up_sync(0xffffffffu, s, o);
            if (lane >= o) s += y;
        }
        ws[lane] = s;
    }
    __syncthreads();
    int excl = x - v + (wid > 0 ? ws[wid - 1] : 0);
    if (tid < nb) g_bsum[tid] = excl;
}

// ---------------- K4c: intra-tile scan + global offset ----------------------
__global__ void __launch_bounds__(SCAN_T)
k_scan3(int N) {
    __shared__ int ws[32];
    int tid = threadIdx.x, lane = tid & 31, wid = tid >> 5;
    int i = blockIdx.x * SCAN_T + tid;
    int v = (i < N) ? g_deg[i] : 0;
    int x = v;
#pragma unroll
    for (int o = 1; o < 32; o <<= 1) {
        int y = __shfl_up_sync(0xffffffffu, x, o);
        if (lane >= o) x += y;
    }
    if (lane == 31) ws[wid] = x;
    __syncthreads();
    if (wid == 0) {
        int s = ws[lane];
#pragma unroll
        for (int o = 1; o < 32; o <<= 1) {
            int y = __shfl_up_sync(0xffffffffu, s, o);
            if (lane >= o) s += y;
        }
        ws[lane] = s;
    }
    __syncthreads();
    int excl = x - v + (wid > 0 ? ws[wid - 1] : 0) + g_bsum[blockIdx.x];
    if (i < N) { g_off[i] = excl; g_cur[i] = excl; }
}

// ---------------- K5: CSR scatter (src only; exp computed in k_agg) ---------
__global__ void k_scatter(const int* __restrict__ EI, int E) {
    int e = blockIdx.x * 256 + threadIdx.x;
    if (e >= E) return;
    int tgt = EI[e], src = EI[E + e];
    int pos = atomicAdd(&g_cur[tgt], 1);
    g_csrc[pos] = src;
}

// ---------------- K6: gather-aggregate + softmax + skip + ELU + LN + mean ---
// block = node; 8 warps split the edge list; each warp covers ALL 256
// channels per edge via ONE uint4 (8 x fp16) load per lane.
// lane covers channels 8*lane..8*lane+7, head = lane>>2.
__global__ void __launch_bounds__(256)
k_agg(const float* __restrict__ gamma, const float* __restrict__ beta,
      const float* __restrict__ ba, int N) {
    int n = blockIdx.x;
    if (n >= N) return;
    const int tid  = threadIdx.x;
    const int wid  = tid >> 5;
    const int lane = tid & 31;
    const int hh   = lane >> 2;          // head of this lane's channels

    __shared__ float s_sib[HEADS];       // si[n][h] + ba[h]
    if (tid < HEADS) s_sib[tid] = g_si[n * HEADS + tid] + ba[tid];
    const int off = g_off[n];
    const int deg = g_deg[n];
    __syncthreads();
    const float sib = (lane < 8) ? s_sib[lane] : 0.f;

    float acc[8];
#pragma unroll
    for (int j = 0; j < 8; j++) acc[j] = 0.f;
    float den = 0.f;

#pragma unroll 4
    for (int k = wid; k < deg; k += 8) {
        int   slot = off + k;
        int   src  = __ldg(&g_csrc[slot]);
        float exv  = 0.f;
        if (lane < 8) {
            float s = sib + __ldg(&g_sj[src * HEADS + lane]);
            s = (s >= 0.f) ? s : SLOPE * s;
            exv = __expf(s);
        }
        float a = __shfl_sync(0xffffffffu, exv, hh);
        uint4 hv = __ldg((const uint4*)&g_Hh[(size_t)src * FDIM] + lane);
        const __half2* hp = (const __half2*)&hv;
        float2 f0 = __half22float2(hp[0]);
        float2 f1 = __half22float2(hp[1]);
        float2 f2 = __half22float2(hp[2]);
        float2 f3 = __half22float2(hp[3]);
        acc[0] = fmaf(a, f0.x, acc[0]); acc[1] = fmaf(a, f0.y, acc[1]);
        acc[2] = fmaf(a, f1.x, acc[2]); acc[3] = fmaf(a, f1.y, acc[3]);
        acc[4] = fmaf(a, f2.x, acc[4]); acc[5] = fmaf(a, f2.y, acc[5]);
        acc[6] = fmaf(a, f3.x, acc[6]); acc[7] = fmaf(a, f3.y, acc[7]);
        den += a;
    }

    __shared__ float sacc[8][FDIM];
    __shared__ float sden[8][HEADS];
    *(float4*)&sacc[wid][lane * 8]     = *(float4*)&acc[0];
    *(float4*)&sacc[wid][lane * 8 + 4] = *(float4*)&acc[4];
    if ((lane & 3) == 0) sden[wid][hh] = den;
    __syncthreads();

    float accf = 0.f, denf = 0.f;
#pragma unroll
    for (int w = 0; w < 8; w++) {
        accf += sacc[w][tid];
        denf += sden[w][tid >> 5];
    }
    float hval = g_H[(size_t)n * FDIM + tid];
    float v = (denf > 0.f ? accf / denf : 0.f) + hval;
    v = (v > 0.f) ? v : expm1f(v);
    float s = v, ss = v * v;
#pragma unroll
    for (int o = 16; o; o >>= 1) {
        s  += __shfl_xor_sync(0xffffffffu, s, o);
        ss += __shfl_xor_sync(0xffffffffu, ss, o);
    }
    float mu  = s * (1.f / HD);
    float var = ss * (1.f / HD) - mu * mu;
    float nrm = (v - mu) * rsqrtf(var + LN_EPS) * gamma[tid] + beta[tid];

    __shared__ float smn[FDIM];
    smn[tid] = nrm;
    __syncthreads();
    if (tid < HD) {
        float m = 0.f;
#pragma unroll
        for (int hx = 0; hx < HEADS; hx++) m += smn[hx * HD + tid];
        g_mean[(size_t)n * HD + tid] = m * (1.f / HEADS);
    }
}

// ---------------- K7: out = ELU(mean @ Wout + bout) -------------------------
__global__ void k_out(const float* __restrict__ Wout,
                      const float* __restrict__ bout,
                      float* __restrict__ out, int N) {
    __shared__ float sm[32][33];
    int row0 = blockIdx.x * 32;
    int tid  = threadIdx.x;
    for (int i = tid; i < 1024; i += 256) {
        int r = i >> 5, d = i & 31;
        sm[r][d] = (row0 + r < N) ? g_mean[(size_t)(row0 + r) * HD + d] : 0.f;
    }
    __syncthreads();
    int col = tid;
    float w[32];
#pragma unroll
    for (int d = 0; d < 32; d++) w[d] = Wout[d * FDIM + col];
    float b = bout[col];
    for (int r = 0; r < 32; r++) {
        if (row0 + r >= N) break;
        float acc = b;
#pragma unroll
        for (int d = 0; d < 32; d++) acc += sm[r][d] * w[d];
        acc = (acc > 0.f) ? acc : expm1f(acc);
        out[(size_t)(row0 + r) * FDIM + col] = acc;
    }
}

// ---------------- launch -----------------------------------------------------
extern "C" void kernel_launch(void* const* d_in, const int* in_sizes, int n_in,
                              void* d_out, int out_size) {
    const float* X    = (const float*)d_in[0];
    const int*   EI   = (const int*)  d_in[1];
    const float* W    = (const float*)d_in[2];
    const float* bw   = (const float*)d_in[3];
    const float* A    = (const float*)d_in[4];
    const float* ba   = (const float*)d_in[5];
    const float* gmm  = (const float*)d_in[6];
    const float* bet  = (const float*)d_in[7];
    const float* Wout = (const float*)d_in[8];
    const float* bout = (const float*)d_in[9];
    float* out = (float*)d_out;

    const int N = in_sizes[0] / FDIM;
    const int E = in_sizes[1] / 2;
    const int nb = (N + SCAN_T - 1) / SCAN_T;

    // CSR build (independent of GEMM)
    k_zero<<<(N + 255) / 256, 256>>>(N);
    k_hist<<<(E + 255) / 256, 256>>>(EI, E);
    k_scan1<<<nb, SCAN_T>>>(N);
    k_scan2<<<1, SCAN_T>>>(nb);
    k_scan3<<<nb, SCAN_T>>>(N);
    k_scatter<<<(E + 255) / 256, 256>>>(EI, E);

    // feature GEMM (tf32 tensor cores) + attention pre-scores
    {
        dim3 grid(FDIM / 128, (N + 127) / 128);
        k_gemm_h<<<grid, 256>>>(X, W, bw, N);
    }
    k_scores<<<N, 256>>>(A, N);

    // fused gather-aggregate + softmax + skip + ELU + LN + head mean
    k_agg<<<N, 256>>>(gmm, bet, ba, N);

    // final projection + ELU
    k_out<<<(N + 31) / 32, 256>>>(Wout, bout, out, N);
}

// round 7
// speedup vs baseline: 2.4368x; 1.1927x over previous
#include <cuda_runtime.h>
#include <cuda_bf16.h>
#include <cuda_fp16.h>
#include <cstdint>

#define N_MAX    50000
#define E_MAX    1600000
#define HEADS    8
#define HD       32
#define FDIM     256          // HEADS*HD == F_IN == HID
#define SLOPE    0.2f
#define LN_EPS   1e-5f
#define SCAN_T   1024

// ---------------- scratch (device globals; no allocation allowed) ----------
__device__ float    g_H   [N_MAX * FDIM];   // h per node (fp32: skip/LN path)
__device__ __half   g_Hh  [N_MAX * FDIM];   // h per node (fp16: gather path)
__device__ float    g_si  [N_MAX * HEADS];
__device__ float    g_sj  [N_MAX * HEADS];
__device__ float    g_mean[N_MAX * HD];
__device__ int      g_deg [N_MAX];
__device__ int      g_off [N_MAX];
__device__ int      g_cur [N_MAX];
__device__ int      g_bsum[1024];
__device__ int      g_csrc[E_MAX];          // CSR: src per slot

// ---------------- K0: zero degree counters ---------------------------------
__global__ void k_zero(int N) {
    int i = blockIdx.x * 256 + threadIdx.x;
    if (i < N) g_deg[i] = 0;
}

__device__ __forceinline__ uint32_t f2tf32(float f) {
    uint32_t t;
    asm("cvt.rna.tf32.f32 %0, %1;" : "=r"(t) : "f"(f));
    return t;
}

// ---------------- K1: H = X @ Wf + bw  (tf32 tensor-core GEMM) --------------
__global__ void __launch_bounds__(256, 2)
k_gemm_h(const float* __restrict__ X, const float* __restrict__ W,
         const float* __restrict__ bw, int N) {
    __shared__ float As[128][36];
    __shared__ float Bs[32][136];

    const int tid  = threadIdx.x;
    const int wid  = tid >> 5, lane = tid & 31;
    const int wm   = (wid & 3) * 32;
    const int wn   = (wid >> 2) * 64;
    const int r    = lane >> 2, c = lane & 3;
    const int row0 = blockIdx.y * 128;
    const int col0 = blockIdx.x * 128;

    float acc[2][8][4];
#pragma unroll
    for (int mf = 0; mf < 2; mf++)
#pragma unroll
        for (int nf = 0; nf < 8; nf++)
#pragma unroll
            for (int i = 0; i < 4; i++) acc[mf][nf][i] = 0.f;

    for (int k0 = 0; k0 < FDIM; k0 += 32) {
#pragma unroll
        for (int i = 0; i < 4; i++) {
            int v = tid + i * 256;
            int m = v >> 3, kq = (v & 7) * 4;
            float4 xv = make_float4(0.f, 0.f, 0.f, 0.f);
            if (row0 + m < N)
                xv = *(const float4*)&X[(size_t)(row0 + m) * FDIM + k0 + kq];
            uint4 tv = make_uint4(f2tf32(xv.x), f2tf32(xv.y),
                                  f2tf32(xv.z), f2tf32(xv.w));
            *(uint4*)&As[m][kq] = tv;
        }
#pragma unroll
        for (int i = 0; i < 4; i++) {
            int v = tid + i * 256;
            int k = v >> 5, n4 = (v & 31) * 4;
            int cc = col0 + n4;
            float4 wv = *(const float4*)
                &W[(size_t)(cc >> 5) * FDIM * HD + (size_t)(k0 + k) * HD + (cc & 31)];
            uint4 tv = make_uint4(f2tf32(wv.x), f2tf32(wv.y),
                                  f2tf32(wv.z), f2tf32(wv.w));
            *(uint4*)&Bs[k][n4] = tv;
        }
        __syncthreads();
#pragma unroll
        for (int kc = 0; kc < 32; kc += 8) {
            uint32_t a[2][4], b[8][2];
#pragma unroll
            for (int mf = 0; mf < 2; mf++) {
                a[mf][0] = __float_as_uint(As[wm + mf * 16 + r    ][kc + c    ]);
                a[mf][1] = __float_as_uint(As[wm + mf * 16 + r + 8][kc + c    ]);
                a[mf][2] = __float_as_uint(As[wm + mf * 16 + r    ][kc + c + 4]);
                a[mf][3] = __float_as_uint(As[wm + mf * 16 + r + 8][kc + c + 4]);
            }
#pragma unroll
            for (int nf = 0; nf < 8; nf++) {
                b[nf][0] = __float_as_uint(Bs[kc + c    ][wn + nf * 8 + r]);
                b[nf][1] = __float_as_uint(Bs[kc + c + 4][wn + nf * 8 + r]);
            }
#pragma unroll
            for (int mf = 0; mf < 2; mf++)
#pragma unroll
                for (int nf = 0; nf < 8; nf++)
                    asm volatile(
                        "mma.sync.aligned.m16n8k8.row.col.f32.tf32.tf32.f32 "
                        "{%0,%1,%2,%3}, {%4,%5,%6,%7}, {%8,%9}, {%0,%1,%2,%3};"
                        : "+f"(acc[mf][nf][0]), "+f"(acc[mf][nf][1]),
                          "+f"(acc[mf][nf][2]), "+f"(acc[mf][nf][3])
                        : "r"(a[mf][0]), "r"(a[mf][1]),
                          "r"(a[mf][2]), "r"(a[mf][3]),
                          "r"(b[nf][0]), "r"(b[nf][1]));
        }
        __syncthreads();
    }
#pragma unroll
    for (int mf = 0; mf < 2; mf++)
#pragma unroll
        for (int i = 0; i < 2; i++) {
            int row = row0 + wm + mf * 16 + r + i * 8;
            if (row < N) {
#pragma unroll
                for (int nf = 0; nf < 8; nf++) {
                    int cc = col0 + wn + nf * 8 + 2 * c;
                    float2 o;
                    o.x = acc[mf][nf][i * 2 + 0] + bw[cc];
                    o.y = acc[mf][nf][i * 2 + 1] + bw[cc + 1];
                    *(float2*)&g_H[(size_t)row * FDIM + cc] = o;
                    *(__half2*)&g_Hh[(size_t)row * FDIM + cc] =
                        __floats2half2_rn(o.x, o.y);
                }
            }
        }
}

// ---------------- K2: si/sj per (node, head) — warp per head ---------------
__global__ void k_scores(const float* __restrict__ A, int N) {
    int n = blockIdx.x;
    if (n >= N) return;
    int h    = threadIdx.x >> 5;
    int lane = threadIdx.x & 31;
    float x  = g_H[(size_t)n * FDIM + h * HD + lane];
    float s1 = x * A[h * 2 * HD + lane];
    float s2 = x * A[h * 2 * HD + HD + lane];
#pragma unroll
    for (int o = 16; o; o >>= 1) {
        s1 += __shfl_xor_sync(0xffffffffu, s1, o);
        s2 += __shfl_xor_sync(0xffffffffu, s2, o);
    }
    if (lane == 0) {
        g_si[n * HEADS + h] = s1;
        g_sj[n * HEADS + h] = s2;
    }
}

// ---------------- K3: degree histogram --------------------------------------
__global__ void k_hist(const int* __restrict__ EI, int E) {
    int e = blockIdx.x * 256 + threadIdx.x;
    if (e < E) atomicAdd(&g_deg[EI[e]], 1);
}

// ---------------- K4a: per-tile totals --------------------------------------
__global__ void __launch_bounds__(SCAN_T)
k_scan1(int N) {
    __shared__ int ws[32];
    int tid = threadIdx.x, lane = tid & 31, wid = tid >> 5;
    int i = blockIdx.x * SCAN_T + tid;
    int v = (i < N) ? g_deg[i] : 0;
#pragma unroll
    for (int o = 16; o; o >>= 1) v += __shfl_xor_sync(0xffffffffu, v, o);
    if (lane == 0) ws[wid] = v;
    __syncthreads();
    if (wid == 0) {
        int s = ws[lane];
#pragma unroll
        for (int o = 16; o; o >>= 1) s += __shfl_xor_sync(0xffffffffu, s, o);
        if (lane == 0) g_bsum[blockIdx.x] = s;
    }
}

// ---------------- K4b: scan tile totals (1 small block) ---------------------
__global__ void __launch_bounds__(SCAN_T)
k_scan2(int nb) {
    __shared__ int ws[32];
    int tid = threadIdx.x, lane = tid & 31, wid = tid >> 5;
    int v = (tid < nb) ? g_bsum[tid] : 0;
    int x = v;
#pragma unroll
    for (int o = 1; o < 32; o <<= 1) {
        int y = __shfl_up_sync(0xffffffffu, x, o);
        if (lane >= o) x += y;
    }
    if (lane == 31) ws[wid] = x;
    __syncthreads();
    if (wid == 0) {
        int s = ws[lane];
#pragma unroll
        for (int o = 1; o < 32; o <<= 1) {
            int y = __shfl_up_sync(0xffffffffu, s, o);
            if (lane >= o) s += y;
        }
        ws[lane] = s;
    }
    __syncthreads();
    int excl = x - v + (wid > 0 ? ws[wid - 1] : 0);
    if (tid < nb) g_bsum[tid] = excl;
}

// ---------------- K4c: intra-tile scan + global offset ----------------------
__global__ void __launch_bounds__(SCAN_T)
k_scan3(int N) {
    __shared__ int ws[32];
    int tid = threadIdx.x, lane = tid & 31, wid = tid >> 5;
    int i = blockIdx.x * SCAN_T + tid;
    int v = (i < N) ? g_deg[i] : 0;
    int x = v;
#pragma unroll
    for (int o = 1; o < 32; o <<= 1) {
        int y = __shfl_up_sync(0xffffffffu, x, o);
        if (lane >= o) x += y;
    }
    if (lane == 31) ws[wid] = x;
    __syncthreads();
    if (wid == 0) {
        int s = ws[lane];
#pragma unroll
        for (int o = 1; o < 32; o <<= 1) {
            int y = __shfl_up_sync(0xffffffffu, s, o);
            if (lane >= o) s += y;
        }
        ws[lane] = s;
    }
    __syncthreads();
    int excl = x - v + (wid > 0 ? ws[wid - 1] : 0) + g_bsum[blockIdx.x];
    if (i < N) { g_off[i] = excl; g_cur[i] = excl; }
}

// ---------------- K5: CSR scatter (src only; exp computed in k_agg) ---------
__global__ void k_scatter(const int* __restrict__ EI, int E) {
    int e = blockIdx.x * 256 + threadIdx.x;
    if (e >= E) return;
    int tgt = EI[e], src = EI[E + e];
    int pos = atomicAdd(&g_cur[tgt], 1);
    g_csrc[pos] = src;
}

// ---------------- K6: warp-per-node gather-aggregate + full epilogue --------
// Warp owns one node. lane covers channels 8*lane..8*lane+7, head = lane>>2.
// All reductions (per-head LN, cross-head mean) are shfl-local; no smem.
__global__ void __launch_bounds__(256)
k_agg(const float* __restrict__ gamma, const float* __restrict__ beta,
      const float* __restrict__ ba, int N) {
    const int lane = threadIdx.x & 31;
    const int n    = blockIdx.x * 8 + (threadIdx.x >> 5);
    if (n >= N) return;
    const int hh   = lane >> 2;          // head of this lane's channels
    const int off  = g_off[n];
    const int deg  = g_deg[n];

    // sib = si[n][lane] + ba[lane] for lanes 0-7 (broadcast source for exp)
    float sib = 0.f;
    if (lane < 8) sib = __ldg(&g_si[n * HEADS + lane]) + __ldg(&ba[lane]);

    float acc[8];
#pragma unroll
    for (int j = 0; j < 8; j++) acc[j] = 0.f;
    float den = 0.f;

#pragma unroll 4
    for (int k = 0; k < deg; k++) {
        int   src  = __ldg(&g_csrc[off + k]);
        float exv  = 0.f;
        if (lane < 8) {
            float s = sib + __ldg(&g_sj[src * HEADS + lane]);
            s = (s >= 0.f) ? s : SLOPE * s;
            exv = __expf(s);
        }
        float a = __shfl_sync(0xffffffffu, exv, hh);
        uint4 hv = __ldg((const uint4*)&g_Hh[(size_t)src * FDIM] + lane);
        const __half2* hp = (const __half2*)&hv;
        float2 f0 = __half22float2(hp[0]);
        float2 f1 = __half22float2(hp[1]);
        float2 f2 = __half22float2(hp[2]);
        float2 f3 = __half22float2(hp[3]);
        acc[0] = fmaf(a, f0.x, acc[0]); acc[1] = fmaf(a, f0.y, acc[1]);
        acc[2] = fmaf(a, f1.x, acc[2]); acc[3] = fmaf(a, f1.y, acc[3]);
        acc[4] = fmaf(a, f2.x, acc[4]); acc[5] = fmaf(a, f2.y, acc[5]);
        acc[6] = fmaf(a, f3.x, acc[6]); acc[7] = fmaf(a, f3.y, acc[7]);
        den += a;
    }
    // den is identical across the 4 lanes of a head (a was broadcast).
    float rden = (den > 0.f) ? 1.f / den : 0.f;

    // skip connection (fp32 path) + ELU
    float4 h0 = *(const float4*)&g_H[(size_t)n * FDIM + lane * 8];
    float4 h1 = *(const float4*)&g_H[(size_t)n * FDIM + lane * 8 + 4];
    float v[8];
    v[0] = acc[0] * rden + h0.x; v[1] = acc[1] * rden + h0.y;
    v[2] = acc[2] * rden + h0.z; v[3] = acc[3] * rden + h0.w;
    v[4] = acc[4] * rden + h1.x; v[5] = acc[5] * rden + h1.y;
    v[6] = acc[6] * rden + h1.z; v[7] = acc[7] * rden + h1.w;
    float s = 0.f, ss = 0.f;
#pragma unroll
    for (int j = 0; j < 8; j++) {
        v[j] = (v[j] > 0.f) ? v[j] : expm1f(v[j]);
        s  += v[j];
        ss += v[j] * v[j];
    }
    // per-head LN stats: reduce over the 4 lanes of this head (xor 1, 2)
    s  += __shfl_xor_sync(0xffffffffu, s, 1);
    ss += __shfl_xor_sync(0xffffffffu, ss, 1);
    s  += __shfl_xor_sync(0xffffffffu, s, 2);
    ss += __shfl_xor_sync(0xffffffffu, ss, 2);
    float mu   = s * (1.f / HD);
    float var  = ss * (1.f / HD) - mu * mu;
    float rstd = rsqrtf(var + LN_EPS);

    const float4 gm0 = *(const float4*)&gamma[lane * 8];
    const float4 gm1 = *(const float4*)&gamma[lane * 8 + 4];
    const float4 bt0 = *(const float4*)&beta [lane * 8];
    const float4 bt1 = *(const float4*)&beta [lane * 8 + 4];
    float nrm[8];
    nrm[0] = (v[0]-mu)*rstd*gm0.x + bt0.x; nrm[1] = (v[1]-mu)*rstd*gm0.y + bt0.y;
    nrm[2] = (v[2]-mu)*rstd*gm0.z + bt0.z; nrm[3] = (v[3]-mu)*rstd*gm0.w + bt0.w;
    nrm[4] = (v[4]-mu)*rstd*gm1.x + bt1.x; nrm[5] = (v[5]-mu)*rstd*gm1.y + bt1.y;
    nrm[6] = (v[6]-mu)*rstd*gm1.z + bt1.z; nrm[7] = (v[7]-mu)*rstd*gm1.w + bt1.w;

    // head-mean: lanes with equal (lane&3) hold same dims across heads
    // (lane = 4h + c, dims = 8c..8c+7) -> reduce over xor 4, 8, 16
#pragma unroll
    for (int j = 0; j < 8; j++) {
        nrm[j] += __shfl_xor_sync(0xffffffffu, nrm[j], 4);
        nrm[j] += __shfl_xor_sync(0xffffffffu, nrm[j], 8);
        nrm[j] += __shfl_xor_sync(0xffffffffu, nrm[j], 16);
        nrm[j] *= (1.f / HEADS);
    }
    if (lane < 4) {
        float4 o0 = make_float4(nrm[0], nrm[1], nrm[2], nrm[3]);
        float4 o1 = make_float4(nrm[4], nrm[5], nrm[6], nrm[7]);
        *(float4*)&g_mean[(size_t)n * HD + lane * 8]     = o0;
        *(float4*)&g_mean[(size_t)n * HD + lane * 8 + 4] = o1;
    }
}

// ---------------- K7: out = ELU(mean @ Wout + bout) -------------------------
__global__ void k_out(const float* __restrict__ Wout,
                      const float* __restrict__ bout,
                      float* __restrict__ out, int N) {
    __shared__ float sm[32][33];
    int row0 = blockIdx.x * 32;
    int tid  = threadIdx.x;
    for (int i = tid; i < 1024; i += 256) {
        int r = i >> 5, d = i & 31;
        sm[r][d] = (row0 + r < N) ? g_mean[(size_t)(row0 + r) * HD + d] : 0.f;
    }
    __syncthreads();
    int col = tid;
    float w[32];
#pragma unroll
    for (int d = 0; d < 32; d++) w[d] = Wout[d * FDIM + col];
    float b = bout[col];
    for (int r = 0; r < 32; r++) {
        if (row0 + r >= N) break;
        float acc = b;
#pragma unroll
        for (int d = 0; d < 32; d++) acc += sm[r][d] * w[d];
        acc = (acc > 0.f) ? acc : expm1f(acc);
        out[(size_t)(row0 + r) * FDIM + col] = acc;
    }
}

// ---------------- launch -----------------------------------------------------
extern "C" void kernel_launch(void* const* d_in, const int* in_sizes, int n_in,
                              void* d_out, int out_size) {
    const float* X    = (const float*)d_in[0];
    const int*   EI   = (const int*)  d_in[1];
    const float* W    = (const float*)d_in[2];
    const float* bw   = (const float*)d_in[3];
    const float* A    = (const float*)d_in[4];
    const float* ba   = (const float*)d_in[5];
    const float* gmm  = (const float*)d_in[6];
    const float* bet  = (const float*)d_in[7];
    const float* Wout = (const float*)d_in[8];
    const float* bout = (const float*)d_in[9];
    float* out = (float*)d_out;

    const int N = in_sizes[0] / FDIM;
    const int E = in_sizes[1] / 2;
    const int nb = (N + SCAN_T - 1) / SCAN_T;

    // CSR build (independent of GEMM)
    k_zero<<<(N + 255) / 256, 256>>>(N);
    k_hist<<<(E + 255) / 256, 256>>>(EI, E);
    k_scan1<<<nb, SCAN_T>>>(N);
    k_scan2<<<1, SCAN_T>>>(nb);
    k_scan3<<<nb, SCAN_T>>>(N);
    k_scatter<<<(E + 255) / 256, 256>>>(EI, E);

    // feature GEMM (tf32 tensor cores) + attention pre-scores
    {
        dim3 grid(FDIM / 128, (N + 127) / 128);
        k_gemm_h<<<grid, 256>>>(X, W, bw, N);
    }
    k_scores<<<N, 256>>>(A, N);

    // warp-per-node gather-aggregate + softmax + skip + ELU + LN + head mean
    k_agg<<<(N + 7) / 8, 256>>>(gmm, bet, ba, N);

    // final projection + ELU
    k_out<<<(N + 31) / 32, 256>>>(Wout, bout, out, N);
}

// round 8
// speedup vs baseline: 2.8688x; 1.1773x over previous
#include <cuda_runtime.h>
#include <cuda_bf16.h>
#include <cuda_fp16.h>
#include <cstdint>

#define N_MAX    50000
#define E_MAX    1600000
#define HEADS    8
#define HD       32
#define FDIM     256          // HEADS*HD == F_IN == HID
#define SLOPE    0.2f
#define LN_EPS   1e-5f
#define SCAN_T   1024

// ---------------- scratch (device globals; no allocation allowed) ----------
__device__ float    g_H   [N_MAX * FDIM];   // h per node (fp32: skip/LN path)
__device__ __half   g_Hh  [N_MAX * FDIM];   // h per node (fp16: gather path)
__device__ float    g_si  [N_MAX * HEADS];
__device__ float    g_sj  [N_MAX * HEADS];
__device__ float    g_mean[N_MAX * HD];
__device__ int      g_deg [N_MAX];
__device__ int      g_off [N_MAX];
__device__ int      g_cur [N_MAX];
__device__ int      g_bsum[1024];
__device__ int      g_csrc[E_MAX];          // CSR: src per slot

// ---------------- K0: zero degree counters ---------------------------------
__global__ void k_zero(int N) {
    int i = blockIdx.x * 256 + threadIdx.x;
    if (i < N) g_deg[i] = 0;
}

__device__ __forceinline__ uint32_t f2tf32(float f) {
    uint32_t t;
    asm("cvt.rna.tf32.f32 %0, %1;" : "=r"(t) : "f"(f));
    return t;
}

// ---------------- K1: H = X @ Wf + bw  (tf32 MMA) + fused si/sj scores ------
// Block tile 128x128. Warp owns rows wm..wm+31, cols wn..wn+63 (= 2 heads),
// so si/sj for those (row, head) pairs are computed in-register in the
// epilogue and reduced across the 4 same-row lanes via shfl.
__global__ void __launch_bounds__(256, 2)
k_gemm_h(const float* __restrict__ X, const float* __restrict__ W,
         const float* __restrict__ bw, const float* __restrict__ Aa, int N) {
    __shared__ float As[128][36];
    __shared__ float Bs[32][136];

    const int tid  = threadIdx.x;
    const int wid  = tid >> 5, lane = tid & 31;
    const int wm   = (wid & 3) * 32;
    const int wn   = (wid >> 2) * 64;
    const int r    = lane >> 2, c = lane & 3;
    const int row0 = blockIdx.y * 128;
    const int col0 = blockIdx.x * 128;

    float acc[2][8][4];
#pragma unroll
    for (int mf = 0; mf < 2; mf++)
#pragma unroll
        for (int nf = 0; nf < 8; nf++)
#pragma unroll
            for (int i = 0; i < 4; i++) acc[mf][nf][i] = 0.f;

    for (int k0 = 0; k0 < FDIM; k0 += 32) {
#pragma unroll
        for (int i = 0; i < 4; i++) {
            int v = tid + i * 256;
            int m = v >> 3, kq = (v & 7) * 4;
            float4 xv = make_float4(0.f, 0.f, 0.f, 0.f);
            if (row0 + m < N)
                xv = *(const float4*)&X[(size_t)(row0 + m) * FDIM + k0 + kq];
            uint4 tv = make_uint4(f2tf32(xv.x), f2tf32(xv.y),
                                  f2tf32(xv.z), f2tf32(xv.w));
            *(uint4*)&As[m][kq] = tv;
        }
#pragma unroll
        for (int i = 0; i < 4; i++) {
            int v = tid + i * 256;
            int k = v >> 5, n4 = (v & 31) * 4;
            int cc = col0 + n4;
            float4 wv = *(const float4*)
                &W[(size_t)(cc >> 5) * FDIM * HD + (size_t)(k0 + k) * HD + (cc & 31)];
            uint4 tv = make_uint4(f2tf32(wv.x), f2tf32(wv.y),
                                  f2tf32(wv.z), f2tf32(wv.w));
            *(uint4*)&Bs[k][n4] = tv;
        }
        __syncthreads();
#pragma unroll
        for (int kc = 0; kc < 32; kc += 8) {
            uint32_t a[2][4], b[8][2];
#pragma unroll
            for (int mf = 0; mf < 2; mf++) {
                a[mf][0] = __float_as_uint(As[wm + mf * 16 + r    ][kc + c    ]);
                a[mf][1] = __float_as_uint(As[wm + mf * 16 + r + 8][kc + c    ]);
                a[mf][2] = __float_as_uint(As[wm + mf * 16 + r    ][kc + c + 4]);
                a[mf][3] = __float_as_uint(As[wm + mf * 16 + r + 8][kc + c + 4]);
            }
#pragma unroll
            for (int nf = 0; nf < 8; nf++) {
                b[nf][0] = __float_as_uint(Bs[kc + c    ][wn + nf * 8 + r]);
                b[nf][1] = __float_as_uint(Bs[kc + c + 4][wn + nf * 8 + r]);
            }
#pragma unroll
            for (int mf = 0; mf < 2; mf++)
#pragma unroll
                for (int nf = 0; nf < 8; nf++)
                    asm volatile(
                        "mma.sync.aligned.m16n8k8.row.col.f32.tf32.tf32.f32 "
                        "{%0,%1,%2,%3}, {%4,%5,%6,%7}, {%8,%9}, {%0,%1,%2,%3};"
                        : "+f"(acc[mf][nf][0]), "+f"(acc[mf][nf][1]),
                          "+f"(acc[mf][nf][2]), "+f"(acc[mf][nf][3])
                        : "r"(a[mf][0]), "r"(a[mf][1]),
                          "r"(a[mf][2]), "r"(a[mf][3]),
                          "r"(b[nf][0]), "r"(b[nf][1]));
        }
        __syncthreads();
    }

    // ---- epilogue: + bw, store fp32 + fp16, fused si/sj ----
    const int hbase = col0 >> 5;           // first head of this block
    const int hA    = hbase + (wn >> 5);   // first head of this warp (2 heads)
    float2 A1[8], A2[8];                   // attention vec frags (nf-dependent)
#pragma unroll
    for (int nf = 0; nf < 8; nf++) {
        int head = hA + (nf >> 2);
        int ch   = (nf & 3) * 8 + 2 * c;
        A1[nf] = *(const float2*)&Aa[head * 2 * HD + ch];
        A2[nf] = *(const float2*)&Aa[head * 2 * HD + HD + ch];
    }
#pragma unroll
    for (int mf = 0; mf < 2; mf++)
#pragma unroll
        for (int i = 0; i < 2; i++) {
            int row = row0 + wm + mf * 16 + r + i * 8;
            bool valid = row < N;
            float s1h[2] = {0.f, 0.f}, s2h[2] = {0.f, 0.f};
#pragma unroll
            for (int nf = 0; nf < 8; nf++) {
                int cc = col0 + wn + nf * 8 + 2 * c;
                float ox = acc[mf][nf][i * 2 + 0] + bw[cc];
                float oy = acc[mf][nf][i * 2 + 1] + bw[cc + 1];
                if (valid) {
                    *(float2*)&g_H[(size_t)row * FDIM + cc] =
                        make_float2(ox, oy);
                    *(__half2*)&g_Hh[(size_t)row * FDIM + cc] =
                        __floats2half2_rn(ox, oy);
                }
                int hl = nf >> 2;
                s1h[hl] += ox * A1[nf].x + oy * A1[nf].y;
                s2h[hl] += ox * A2[nf].x + oy * A2[nf].y;
            }
            // reduce across the 4 lanes sharing this row (xor 1, 2)
#pragma unroll
            for (int hl = 0; hl < 2; hl++) {
                s1h[hl] += __shfl_xor_sync(0xffffffffu, s1h[hl], 1);
                s1h[hl] += __shfl_xor_sync(0xffffffffu, s1h[hl], 2);
                s2h[hl] += __shfl_xor_sync(0xffffffffu, s2h[hl], 1);
                s2h[hl] += __shfl_xor_sync(0xffffffffu, s2h[hl], 2);
            }
            if (valid && c == 0) {
                g_si[row * HEADS + hA]     = s1h[0];
                g_sj[row * HEADS + hA]     = s2h[0];
                g_si[row * HEADS + hA + 1] = s1h[1];
                g_sj[row * HEADS + hA + 1] = s2h[1];
            }
        }
}

// ---------------- K3: degree histogram --------------------------------------
__global__ void k_hist(const int* __restrict__ EI, int E) {
    int e = blockIdx.x * 256 + threadIdx.x;
    if (e < E) atomicAdd(&g_deg[EI[e]], 1);
}

// ---------------- K4a: per-tile totals --------------------------------------
__global__ void __launch_bounds__(SCAN_T)
k_scan1(int N) {
    __shared__ int ws[32];
    int tid = threadIdx.x, lane = tid & 31, wid = tid >> 5;
    int i = blockIdx.x * SCAN_T + tid;
    int v = (i < N) ? g_deg[i] : 0;
#pragma unroll
    for (int o = 16; o; o >>= 1) v += __shfl_xor_sync(0xffffffffu, v, o);
    if (lane == 0) ws[wid] = v;
    __syncthreads();
    if (wid == 0) {
        int s = ws[lane];
#pragma unroll
        for (int o = 16; o; o >>= 1) s += __shfl_xor_sync(0xffffffffu, s, o);
        if (lane == 0) g_bsum[blockIdx.x] = s;
    }
}

// ---------------- K4b: scan tile totals (1 small block) ---------------------
__global__ void __launch_bounds__(SCAN_T)
k_scan2(int nb) {
    __shared__ int ws[32];
    int tid = threadIdx.x, lane = tid & 31, wid = tid >> 5;
    int v = (tid < nb) ? g_bsum[tid] : 0;
    int x = v;
#pragma unroll
    for (int o = 1; o < 32; o <<= 1) {
        int y = __shfl_up_sync(0xffffffffu, x, o);
        if (lane >= o) x += y;
    }
    if (lane == 31) ws[wid] = x;
    __syncthreads();
    if (wid == 0) {
        int s = ws[lane];
#pragma unroll
        for (int o = 1; o < 32; o <<= 1) {
            int y = __shfl_up_sync(0xffffffffu, s, o);
            if (lane >= o) s += y;
        }
        ws[lane] = s;
    }
    __syncthreads();
    int excl = x - v + (wid > 0 ? ws[wid - 1] : 0);
    if (tid < nb) g_bsum[tid] = excl;
}

// ---------------- K4c: intra-tile scan + global offset ----------------------
__global__ void __launch_bounds__(SCAN_T)
k_scan3(int N) {
    __shared__ int ws[32];
    int tid = threadIdx.x, lane = tid & 31, wid = tid >> 5;
    int i = blockIdx.x * SCAN_T + tid;
    int v = (i < N) ? g_deg[i] : 0;
    int x = v;
#pragma unroll
    for (int o = 1; o < 32; o <<= 1) {
        int y = __shfl_up_sync(0xffffffffu, x, o);
        if (lane >= o) x += y;
    }
    if (lane == 31) ws[wid] = x;
    __syncthreads();
    if (wid == 0) {
        int s = ws[lane];
#pragma unroll
        for (int o = 1; o < 32; o <<= 1) {
            int y = __shfl_up_sync(0xffffffffu, s, o);
            if (lane >= o) s += y;
        }
        ws[lane] = s;
    }
    __syncthreads();
    int excl = x - v + (wid > 0 ? ws[wid - 1] : 0) + g_bsum[blockIdx.x];
    if (i < N) { g_off[i] = excl; g_cur[i] = excl; }
}

// ---------------- K5: CSR scatter (src only; exp computed in k_agg) ---------
__global__ void k_scatter(const int* __restrict__ EI, int E) {
    int e = blockIdx.x * 256 + threadIdx.x;
    if (e >= E) return;
    int tgt = EI[e], src = EI[E + e];
    int pos = atomicAdd(&g_cur[tgt], 1);
    g_csrc[pos] = src;
}

// ---------------- K6: warp-per-node gather-aggregate + full epilogue --------
__global__ void __launch_bounds__(256)
k_agg(const float* __restrict__ gamma, const float* __restrict__ beta,
      const float* __restrict__ ba, int N) {
    const int lane = threadIdx.x & 31;
    const int n    = blockIdx.x * 8 + (threadIdx.x >> 5);
    if (n >= N) return;
    const int hh   = lane >> 2;          // head of this lane's channels
    const int off  = g_off[n];
    const int deg  = g_deg[n];

    float sib = 0.f;
    if (lane < 8) sib = __ldg(&g_si[n * HEADS + lane]) + __ldg(&ba[lane]);

    float acc[8];
#pragma unroll
    for (int j = 0; j < 8; j++) acc[j] = 0.f;
    float den = 0.f;

#pragma unroll 4
    for (int k = 0; k < deg; k++) {
        int   src  = __ldg(&g_csrc[off + k]);
        float exv  = 0.f;
        if (lane < 8) {
            float s = sib + __ldg(&g_sj[src * HEADS + lane]);
            s = (s >= 0.f) ? s : SLOPE * s;
            exv = __expf(s);
        }
        float a = __shfl_sync(0xffffffffu, exv, hh);
        uint4 hv = __ldg((const uint4*)&g_Hh[(size_t)src * FDIM] + lane);
        const __half2* hp = (const __half2*)&hv;
        float2 f0 = __half22float2(hp[0]);
        float2 f1 = __half22float2(hp[1]);
        float2 f2 = __half22float2(hp[2]);
        float2 f3 = __half22float2(hp[3]);
        acc[0] = fmaf(a, f0.x, acc[0]); acc[1] = fmaf(a, f0.y, acc[1]);
        acc[2] = fmaf(a, f1.x, acc[2]); acc[3] = fmaf(a, f1.y, acc[3]);
        acc[4] = fmaf(a, f2.x, acc[4]); acc[5] = fmaf(a, f2.y, acc[5]);
        acc[6] = fmaf(a, f3.x, acc[6]); acc[7] = fmaf(a, f3.y, acc[7]);
        den += a;
    }
    float rden = (den > 0.f) ? 1.f / den : 0.f;

    float4 h0 = *(const float4*)&g_H[(size_t)n * FDIM + lane * 8];
    float4 h1 = *(const float4*)&g_H[(size_t)n * FDIM + lane * 8 + 4];
    float v[8];
    v[0] = acc[0] * rden + h0.x; v[1] = acc[1] * rden + h0.y;
    v[2] = acc[2] * rden + h0.z; v[3] = acc[3] * rden + h0.w;
    v[4] = acc[4] * rden + h1.x; v[5] = acc[5] * rden + h1.y;
    v[6] = acc[6] * rden + h1.z; v[7] = acc[7] * rden + h1.w;
    float s = 0.f, ss = 0.f;
#pragma unroll
    for (int j = 0; j < 8; j++) {
        v[j] = (v[j] > 0.f) ? v[j] : expm1f(v[j]);
        s  += v[j];
        ss += v[j] * v[j];
    }
    s  += __shfl_xor_sync(0xffffffffu, s, 1);
    ss += __shfl_xor_sync(0xffffffffu, ss, 1);
    s  += __shfl_xor_sync(0xffffffffu, s, 2);
    ss += __shfl_xor_sync(0xffffffffu, ss, 2);
    float mu   = s * (1.f / HD);
    float var  = ss * (1.f / HD) - mu * mu;
    float rstd = rsqrtf(var + LN_EPS);

    const float4 gm0 = *(const float4*)&gamma[lane * 8];
    const float4 gm1 = *(const float4*)&gamma[lane * 8 + 4];
    const float4 bt0 = *(const float4*)&beta [lane * 8];
    const float4 bt1 = *(const float4*)&beta [lane * 8 + 4];
    float nrm[8];
    nrm[0] = (v[0]-mu)*rstd*gm0.x + bt0.x; nrm[1] = (v[1]-mu)*rstd*gm0.y + bt0.y;
    nrm[2] = (v[2]-mu)*rstd*gm0.z + bt0.z; nrm[3] = (v[3]-mu)*rstd*gm0.w + bt0.w;
    nrm[4] = (v[4]-mu)*rstd*gm1.x + bt1.x; nrm[5] = (v[5]-mu)*rstd*gm1.y + bt1.y;
    nrm[6] = (v[6]-mu)*rstd*gm1.z + bt1.z; nrm[7] = (v[7]-mu)*rstd*gm1.w + bt1.w;

#pragma unroll
    for (int j = 0; j < 8; j++) {
        nrm[j] += __shfl_xor_sync(0xffffffffu, nrm[j], 4);
        nrm[j] += __shfl_xor_sync(0xffffffffu, nrm[j], 8);
        nrm[j] += __shfl_xor_sync(0xffffffffu, nrm[j], 16);
        nrm[j] *= (1.f / HEADS);
    }
    if (lane < 4) {
        float4 o0 = make_float4(nrm[0], nrm[1], nrm[2], nrm[3]);
        float4 o1 = make_float4(nrm[4], nrm[5], nrm[6], nrm[7]);
        *(float4*)&g_mean[(size_t)n * HD + lane * 8]     = o0;
        *(float4*)&g_mean[(size_t)n * HD + lane * 8 + 4] = o1;
    }
}

// ---------------- K7: out = ELU(mean @ Wout + bout) -------------------------
__global__ void k_out(const float* __restrict__ Wout,
                      const float* __restrict__ bout,
                      float* __restrict__ out, int N) {
    __shared__ float sm[32][33];
    int row0 = blockIdx.x * 32;
    int tid  = threadIdx.x;
    for (int i = tid; i < 1024; i += 256) {
        int r = i >> 5, d = i & 31;
        sm[r][d] = (row0 + r < N) ? g_mean[(size_t)(row0 + r) * HD + d] : 0.f;
    }
    __syncthreads();
    int col = tid;
    float w[32];
#pragma unroll
    for (int d = 0; d < 32; d++) w[d] = Wout[d * FDIM + col];
    float b = bout[col];
    for (int r = 0; r < 32; r++) {
        if (row0 + r >= N) break;
        float acc = b;
#pragma unroll
        for (int d = 0; d < 32; d++) acc += sm[r][d] * w[d];
        acc = (acc > 0.f) ? acc : expm1f(acc);
        out[(size_t)(row0 + r) * FDIM + col] = acc;
    }
}

// ---------------- launch -----------------------------------------------------
extern "C" void kernel_launch(void* const* d_in, const int* in_sizes, int n_in,
                              void* d_out, int out_size) {
    const float* X    = (const float*)d_in[0];
    const int*   EI   = (const int*)  d_in[1];
    const float* W    = (const float*)d_in[2];
    const float* bw   = (const float*)d_in[3];
    const float* A    = (const float*)d_in[4];
    const float* ba   = (const float*)d_in[5];
    const float* gmm  = (const float*)d_in[6];
    const float* bet  = (const float*)d_in[7];
    const float* Wout = (const float*)d_in[8];
    const float* bout = (const float*)d_in[9];
    float* out = (float*)d_out;

    const int N = in_sizes[0] / FDIM;
    const int E = in_sizes[1] / 2;
    const int nb = (N + SCAN_T - 1) / SCAN_T;

    // One-time host-side resources (no device memory involved).
    static cudaStream_t s_side = nullptr;
    static cudaEvent_t  ev_fork = nullptr, ev_join = nullptr;
    if (s_side == nullptr) {
        cudaStreamCreateWithFlags(&s_side, cudaStreamNonBlocking);
        cudaEventCreateWithFlags(&ev_fork, cudaEventDisableTiming);
        cudaEventCreateWithFlags(&ev_join, cudaEventDisableTiming);
    }

    // fork: CSR build runs on side stream, concurrent with the GEMM
    cudaEventRecord(ev_fork, 0);
    cudaStreamWaitEvent(s_side, ev_fork, 0);

    k_zero   <<<(N + 255) / 256, 256, 0, s_side>>>(N);
    k_hist   <<<(E + 255) / 256, 256, 0, s_side>>>(EI, E);
    k_scan1  <<<nb, SCAN_T, 0, s_side>>>(N);
    k_scan2  <<<1,  SCAN_T, 0, s_side>>>(nb);
    k_scan3  <<<nb, SCAN_T, 0, s_side>>>(N);
    k_scatter<<<(E + 255) / 256, 256, 0, s_side>>>(EI, E);
    cudaEventRecord(ev_join, s_side);

    // main stream: feature GEMM with fused si/sj scores
    {
        dim3 grid(FDIM / 128, (N + 127) / 128);
        k_gemm_h<<<grid, 256>>>(X, W, bw, A, N);
    }

    // join, then aggregate + output
    cudaStreamWaitEvent(0, ev_join, 0);
    k_agg<<<(N + 7) / 8, 256>>>(gmm, bet, ba, N);
    k_out<<<(N + 31) / 32, 256>>>(Wout, bout, out, N);
}

// round 9
// speedup vs baseline: 3.2492x; 1.1326x over previous
#include <cuda_runtime.h>
#include <cuda_bf16.h>
#include <cuda_fp16.h>
#include <cstdint>

#define N_MAX    50000
#define E_MAX    1600000
#define HEADS    8
#define HD       32
#define FDIM     256          // HEADS*HD == F_IN == HID
#define SLOPE    0.2f
#define LN_EPS   1e-5f
#define SCAN_T   1024

// ---------------- scratch (device globals; no allocation allowed) ----------
__device__ __half   g_Hh  [N_MAX * FDIM];   // h per node (fp16)
__device__ float    g_si  [N_MAX * HEADS];
__device__ float    g_sj  [N_MAX * HEADS];
__device__ float    g_mean[N_MAX * HD];
__device__ int      g_deg [N_MAX];
__device__ int      g_off [N_MAX];
__device__ int      g_cur [N_MAX];
__device__ int      g_bsum[1024];
__device__ int      g_csrc[E_MAX];          // CSR: src per slot

// ---------------- K0: zero degree counters ---------------------------------
__global__ void k_zero(int N) {
    int i = blockIdx.x * 256 + threadIdx.x;
    if (i < N) g_deg[i] = 0;
}

__device__ __forceinline__ uint32_t f2tf32(float f) {
    uint32_t t;
    asm("cvt.rna.tf32.f32 %0, %1;" : "=r"(t) : "f"(f));
    return t;
}

// ---------------- K1: H = X @ Wf + bw  (tf32 MMA) + fused si/sj scores ------
__global__ void __launch_bounds__(256, 2)
k_gemm_h(const float* __restrict__ X, const float* __restrict__ W,
         const float* __restrict__ bw, const float* __restrict__ Aa, int N) {
    __shared__ float As[128][36];
    __shared__ float Bs[32][136];

    const int tid  = threadIdx.x;
    const int wid  = tid >> 5, lane = tid & 31;
    const int wm   = (wid & 3) * 32;
    const int wn   = (wid >> 2) * 64;
    const int r    = lane >> 2, c = lane & 3;
    const int row0 = blockIdx.y * 128;
    const int col0 = blockIdx.x * 128;

    float acc[2][8][4];
#pragma unroll
    for (int mf = 0; mf < 2; mf++)
#pragma unroll
        for (int nf = 0; nf < 8; nf++)
#pragma unroll
            for (int i = 0; i < 4; i++) acc[mf][nf][i] = 0.f;

    for (int k0 = 0; k0 < FDIM; k0 += 32) {
#pragma unroll
        for (int i = 0; i < 4; i++) {
            int v = tid + i * 256;
            int m = v >> 3, kq = (v & 7) * 4;
            float4 xv = make_float4(0.f, 0.f, 0.f, 0.f);
            if (row0 + m < N)
                xv = *(const float4*)&X[(size_t)(row0 + m) * FDIM + k0 + kq];
            uint4 tv = make_uint4(f2tf32(xv.x), f2tf32(xv.y),
                                  f2tf32(xv.z), f2tf32(xv.w));
            *(uint4*)&As[m][kq] = tv;
        }
#pragma unroll
        for (int i = 0; i < 4; i++) {
            int v = tid + i * 256;
            int k = v >> 5, n4 = (v & 31) * 4;
            int cc = col0 + n4;
            float4 wv = *(const float4*)
                &W[(size_t)(cc >> 5) * FDIM * HD + (size_t)(k0 + k) * HD + (cc & 31)];
            uint4 tv = make_uint4(f2tf32(wv.x), f2tf32(wv.y),
                                  f2tf32(wv.z), f2tf32(wv.w));
            *(uint4*)&Bs[k][n4] = tv;
        }
        __syncthreads();
#pragma unroll
        for (int kc = 0; kc < 32; kc += 8) {
            uint32_t a[2][4], b[8][2];
#pragma unroll
            for (int mf = 0; mf < 2; mf++) {
                a[mf][0] = __float_as_uint(As[wm + mf * 16 + r    ][kc + c    ]);
                a[mf][1] = __float_as_uint(As[wm + mf * 16 + r + 8][kc + c    ]);
                a[mf][2] = __float_as_uint(As[wm + mf * 16 + r    ][kc + c + 4]);
                a[mf][3] = __float_as_uint(As[wm + mf * 16 + r + 8][kc + c + 4]);
            }
#pragma unroll
            for (int nf = 0; nf < 8; nf++) {
                b[nf][0] = __float_as_uint(Bs[kc + c    ][wn + nf * 8 + r]);
                b[nf][1] = __float_as_uint(Bs[kc + c + 4][wn + nf * 8 + r]);
            }
#pragma unroll
            for (int mf = 0; mf < 2; mf++)
#pragma unroll
                for (int nf = 0; nf < 8; nf++)
                    asm volatile(
                        "mma.sync.aligned.m16n8k8.row.col.f32.tf32.tf32.f32 "
                        "{%0,%1,%2,%3}, {%4,%5,%6,%7}, {%8,%9}, {%0,%1,%2,%3};"
                        : "+f"(acc[mf][nf][0]), "+f"(acc[mf][nf][1]),
                          "+f"(acc[mf][nf][2]), "+f"(acc[mf][nf][3])
                        : "r"(a[mf][0]), "r"(a[mf][1]),
                          "r"(a[mf][2]), "r"(a[mf][3]),
                          "r"(b[nf][0]), "r"(b[nf][1]));
        }
        __syncthreads();
    }

    // ---- epilogue: + bw, store fp16, fused si/sj ----
    const int hbase = col0 >> 5;
    const int hA    = hbase + (wn >> 5);
    float2 A1[8], A2[8];
#pragma unroll
    for (int nf = 0; nf < 8; nf++) {
        int head = hA + (nf >> 2);
        int ch   = (nf & 3) * 8 + 2 * c;
        A1[nf] = *(const float2*)&Aa[head * 2 * HD + ch];
        A2[nf] = *(const float2*)&Aa[head * 2 * HD + HD + ch];
    }
#pragma unroll
    for (int mf = 0; mf < 2; mf++)
#pragma unroll
        for (int i = 0; i < 2; i++) {
            int row = row0 + wm + mf * 16 + r + i * 8;
            bool valid = row < N;
            float s1h[2] = {0.f, 0.f}, s2h[2] = {0.f, 0.f};
#pragma unroll
            for (int nf = 0; nf < 8; nf++) {
                int cc = col0 + wn + nf * 8 + 2 * c;
                float ox = acc[mf][nf][i * 2 + 0] + bw[cc];
                float oy = acc[mf][nf][i * 2 + 1] + bw[cc + 1];
                if (valid)
                    *(__half2*)&g_Hh[(size_t)row * FDIM + cc] =
                        __floats2half2_rn(ox, oy);
                int hl = nf >> 2;
                s1h[hl] += ox * A1[nf].x + oy * A1[nf].y;
                s2h[hl] += ox * A2[nf].x + oy * A2[nf].y;
            }
#pragma unroll
            for (int hl = 0; hl < 2; hl++) {
                s1h[hl] += __shfl_xor_sync(0xffffffffu, s1h[hl], 1);
                s1h[hl] += __shfl_xor_sync(0xffffffffu, s1h[hl], 2);
                s2h[hl] += __shfl_xor_sync(0xffffffffu, s2h[hl], 1);
                s2h[hl] += __shfl_xor_sync(0xffffffffu, s2h[hl], 2);
            }
            if (valid && c == 0) {
                g_si[row * HEADS + hA]     = s1h[0];
                g_sj[row * HEADS + hA]     = s2h[0];
                g_si[row * HEADS + hA + 1] = s1h[1];
                g_sj[row * HEADS + hA + 1] = s2h[1];
            }
        }
}

// ---------------- K3: degree histogram --------------------------------------
__global__ void k_hist(const int* __restrict__ EI, int E) {
    int e = blockIdx.x * 256 + threadIdx.x;
    if (e < E) atomicAdd(&g_deg[EI[e]], 1);
}

// ---------------- K4a: per-tile totals --------------------------------------
__global__ void __launch_bounds__(SCAN_T)
k_scan1(int N) {
    __shared__ int ws[32];
    int tid = threadIdx.x, lane = tid & 31, wid = tid >> 5;
    int i = blockIdx.x * SCAN_T + tid;
    int v = (i < N) ? g_deg[i] : 0;
#pragma unroll
    for (int o = 16; o; o >>= 1) v += __shfl_xor_sync(0xffffffffu, v, o);
    if (lane == 0) ws[wid] = v;
    __syncthreads();
    if (wid == 0) {
        int s = ws[lane];
#pragma unroll
        for (int o = 16; o; o >>= 1) s += __shfl_xor_sync(0xffffffffu, s, o);
        if (lane == 0) g_bsum[blockIdx.x] = s;
    }
}

// ---------------- K4b: scan tile totals (1 small block) ---------------------
__global__ void __launch_bounds__(SCAN_T)
k_scan2(int nb) {
    __shared__ int ws[32];
    int tid = threadIdx.x, lane = tid & 31, wid = tid >> 5;
    int v = (tid < nb) ? g_bsum[tid] : 0;
    int x = v;
#pragma unroll
    for (int o = 1; o < 32; o <<= 1) {
        int y = __shfl_up_sync(0xffffffffu, x, o);
        if (lane >= o) x += y;
    }
    if (lane == 31) ws[wid] = x;
    __syncthreads();
    if (wid == 0) {
        int s = ws[lane];
#pragma unroll
        for (int o = 1; o < 32; o <<= 1) {
            int y = __shfl_up_sync(0xffffffffu, s, o);
            if (lane >= o) s += y;
        }
        ws[lane] = s;
    }
    __syncthreads();
    int excl = x - v + (wid > 0 ? ws[wid - 1] : 0);
    if (tid < nb) g_bsum[tid] = excl;
}

// ---------------- K4c: intra-tile scan + global offset ----------------------
__global__ void __launch_bounds__(SCAN_T)
k_scan3(int N) {
    __shared__ int ws[32];
    int tid = threadIdx.x, lane = tid & 31, wid = tid >> 5;
    int i = blockIdx.x * SCAN_T + tid;
    int v = (i < N) ? g_deg[i] : 0;
    int x = v;
#pragma unroll
    for (int o = 1; o < 32; o <<= 1) {
        int y = __shfl_up_sync(0xffffffffu, x, o);
        if (lane >= o) x += y;
    }
    if (lane == 31) ws[wid] = x;
    __syncthreads();
    if (wid == 0) {
        int s = ws[lane];
#pragma unroll
        for (int o = 1; o < 32; o <<= 1) {
            int y = __shfl_up_sync(0xffffffffu, s, o);
            if (lane >= o) s += y;
        }
        ws[lane] = s;
    }
    __syncthreads();
    int excl = x - v + (wid > 0 ? ws[wid - 1] : 0) + g_bsum[blockIdx.x];
    if (i < N) { g_off[i] = excl; g_cur[i] = excl; }
}

// ---------------- K5: CSR scatter (src only) --------------------------------
__global__ void k_scatter(const int* __restrict__ EI, int E) {
    int e = blockIdx.x * 256 + threadIdx.x;
    if (e >= E) return;
    int tgt = EI[e], src = EI[E + e];
    int pos = atomicAdd(&g_cur[tgt], 1);
    g_csrc[pos] = src;
}

// ---------------- K6: warp-per-node gather-aggregate + full epilogue --------
// 4 edges per step: lane = e*8 + h computes exp for (edge k+e, head h), so
// exp/sj/csrc loads use all 32 lanes. Hh gathers depend only on the src
// shfl and issue ahead of the exp chain.
__global__ void __launch_bounds__(256)
k_agg(const float* __restrict__ gamma, const float* __restrict__ beta,
      const float* __restrict__ ba, int N) {
    const int lane = threadIdx.x & 31;
    const int n    = blockIdx.x * 8 + (threadIdx.x >> 5);
    if (n >= N) return;
    const int hh   = lane >> 2;          // head of this lane's 8 channels
    const int off  = g_off[n];
    const int deg  = g_deg[n];

    // sib for head (lane&7) replicated to all lanes
    float sib0 = 0.f;
    if (lane < 8) sib0 = __ldg(&g_si[n * HEADS + lane]) + __ldg(&ba[lane]);
    const float sib  = __shfl_sync(0xffffffffu, sib0, lane & 7);
    const int   eh_e = lane >> 3;        // edge slot (0..3) for exp duty
    const int   eh_h = lane & 7;         // head for exp duty

    float acc[8];
#pragma unroll
    for (int j = 0; j < 8; j++) acc[j] = 0.f;
    float den = 0.f;

#pragma unroll 2
    for (int k = 0; k < deg; k += 4) {
        int s4 = 0;
        if (lane < 4) {
            int idx = k + lane;
            s4 = __ldg(&g_csrc[off + (idx < deg ? idx : deg - 1)]);
        }
        int   src_l = __shfl_sync(0xffffffffu, s4, eh_e);
        float sc    = sib + __ldg(&g_sj[src_l * HEADS + eh_h]);
        sc = (sc >= 0.f) ? sc : SLOPE * sc;
        float exv = (k + eh_e < deg) ? __expf(sc) : 0.f;
#pragma unroll
        for (int ee = 0; ee < 4; ee++) {
            int   srce = __shfl_sync(0xffffffffu, s4, ee);
            uint4 hv = __ldg((const uint4*)&g_Hh[(size_t)srce * FDIM] + lane);
            float a  = __shfl_sync(0xffffffffu, exv, ee * 8 + hh);
            const __half2* hp = (const __half2*)&hv;
            float2 f0 = __half22float2(hp[0]);
            float2 f1 = __half22float2(hp[1]);
            float2 f2 = __half22float2(hp[2]);
            float2 f3 = __half22float2(hp[3]);
            acc[0] = fmaf(a, f0.x, acc[0]); acc[1] = fmaf(a, f0.y, acc[1]);
            acc[2] = fmaf(a, f1.x, acc[2]); acc[3] = fmaf(a, f1.y, acc[3]);
            acc[4] = fmaf(a, f2.x, acc[4]); acc[5] = fmaf(a, f2.y, acc[5]);
            acc[6] = fmaf(a, f3.x, acc[6]); acc[7] = fmaf(a, f3.y, acc[7]);
            den += a;
        }
    }
    float rden = (den > 0.f) ? 1.f / den : 0.f;

    // skip connection (fp16) + ELU
    uint4 hs = *((const uint4*)&g_Hh[(size_t)n * FDIM] + lane);
    const __half2* sp = (const __half2*)&hs;
    float2 s0 = __half22float2(sp[0]);
    float2 s1 = __half22float2(sp[1]);
    float2 s2 = __half22float2(sp[2]);
    float2 s3 = __half22float2(sp[3]);
    float v[8];
    v[0] = acc[0] * rden + s0.x; v[1] = acc[1] * rden + s0.y;
    v[2] = acc[2] * rden + s1.x; v[3] = acc[3] * rden + s1.y;
    v[4] = acc[4] * rden + s2.x; v[5] = acc[5] * rden + s2.y;
    v[6] = acc[6] * rden + s3.x; v[7] = acc[7] * rden + s3.y;
    float s = 0.f, ss = 0.f;
#pragma unroll
    for (int j = 0; j < 8; j++) {
        v[j] = (v[j] > 0.f) ? v[j] : expm1f(v[j]);
        s  += v[j];
        ss += v[j] * v[j];
    }
    s  += __shfl_xor_sync(0xffffffffu, s, 1);
    ss += __shfl_xor_sync(0xffffffffu, ss, 1);
    s  += __shfl_xor_sync(0xffffffffu, s, 2);
    ss += __shfl_xor_sync(0xffffffffu, ss, 2);
    float mu   = s * (1.f / HD);
    float var  = ss * (1.f / HD) - mu * mu;
    float rstd = rsqrtf(var + LN_EPS);

    const float4 gm0 = *(const float4*)&gamma[lane * 8];
    const float4 gm1 = *(const float4*)&gamma[lane * 8 + 4];
    const float4 bt0 = *(const float4*)&beta [lane * 8];
    const float4 bt1 = *(const float4*)&beta [lane * 8 + 4];
    float nrm[8];
    nrm[0] = (v[0]-mu)*rstd*gm0.x + bt0.x; nrm[1] = (v[1]-mu)*rstd*gm0.y + bt0.y;
    nrm[2] = (v[2]-mu)*rstd*gm0.z + bt0.z; nrm[3] = (v[3]-mu)*rstd*gm0.w + bt0.w;
    nrm[4] = (v[4]-mu)*rstd*gm1.x + bt1.x; nrm[5] = (v[5]-mu)*rstd*gm1.y + bt1.y;
    nrm[6] = (v[6]-mu)*rstd*gm1.z + bt1.z; nrm[7] = (v[7]-mu)*rstd*gm1.w + bt1.w;

#pragma unroll
    for (int j = 0; j < 8; j++) {
        nrm[j] += __shfl_xor_sync(0xffffffffu, nrm[j], 4);
        nrm[j] += __shfl_xor_sync(0xffffffffu, nrm[j], 8);
        nrm[j] += __shfl_xor_sync(0xffffffffu, nrm[j], 16);
        nrm[j] *= (1.f / HEADS);
    }
    if (lane < 4) {
        float4 o0 = make_float4(nrm[0], nrm[1], nrm[2], nrm[3]);
        float4 o1 = make_float4(nrm[4], nrm[5], nrm[6], nrm[7]);
        *(float4*)&g_mean[(size_t)n * HD + lane * 8]     = o0;
        *(float4*)&g_mean[(size_t)n * HD + lane * 8 + 4] = o1;
    }
}

// ---------------- K7: out = ELU(mean @ Wout + bout) -------------------------
__global__ void k_out(const float* __restrict__ Wout,
                      const float* __restrict__ bout,
                      float* __restrict__ out, int N) {
    __shared__ float sm[32][33];
    int row0 = blockIdx.x * 32;
    int tid  = threadIdx.x;
    for (int i = tid; i < 1024; i += 256) {
        int r = i >> 5, d = i & 31;
        sm[r][d] = (row0 + r < N) ? g_mean[(size_t)(row0 + r) * HD + d] : 0.f;
    }
    __syncthreads();
    int col = tid;
    float w[32];
#pragma unroll
    for (int d = 0; d < 32; d++) w[d] = Wout[d * FDIM + col];
    float b = bout[col];
    for (int r = 0; r < 32; r++) {
        if (row0 + r >= N) break;
        float acc = b;
#pragma unroll
        for (int d = 0; d < 32; d++) acc += sm[r][d] * w[d];
        acc = (acc > 0.f) ? acc : expm1f(acc);
        out[(size_t)(row0 + r) * FDIM + col] = acc;
    }
}

// ---------------- launch -----------------------------------------------------
extern "C" void kernel_launch(void* const* d_in, const int* in_sizes, int n_in,
                              void* d_out, int out_size) {
    const float* X    = (const float*)d_in[0];
    const int*   EI   = (const int*)  d_in[1];
    const float* W    = (const float*)d_in[2];
    const float* bw   = (const float*)d_in[3];
    const float* A    = (const float*)d_in[4];
    const float* ba   = (const float*)d_in[5];
    const float* gmm  = (const float*)d_in[6];
    const float* bet  = (const float*)d_in[7];
    const float* Wout = (const float*)d_in[8];
    const float* bout = (const float*)d_in[9];
    float* out = (float*)d_out;

    const int N = in_sizes[0] / FDIM;
    const int E = in_sizes[1] / 2;
    const int nb = (N + SCAN_T - 1) / SCAN_T;

    static cudaStream_t s_side = nullptr;
    static cudaEvent_t  ev_fork = nullptr, ev_join = nullptr;
    if (s_side == nullptr) {
        cudaStreamCreateWithFlags(&s_side, cudaStreamNonBlocking);
        cudaEventCreateWithFlags(&ev_fork, cudaEventDisableTiming);
        cudaEventCreateWithFlags(&ev_join, cudaEventDisableTiming);
    }

    // fork: CSR build runs on side stream, concurrent with the GEMM
    cudaEventRecord(ev_fork, 0);
    cudaStreamWaitEvent(s_side, ev_fork, 0);

    k_zero   <<<(N + 255) / 256, 256, 0, s_side>>>(N);
    k_hist   <<<(E + 255) / 256, 256, 0, s_side>>>(EI, E);
    k_scan1  <<<nb, SCAN_T, 0, s_side>>>(N);
    k_scan2  <<<1,  SCAN_T, 0, s_side>>>(nb);
    k_scan3  <<<nb, SCAN_T, 0, s_side>>>(N);
    k_scatter<<<(E + 255) / 256, 256, 0, s_side>>>(EI, E);
    cudaEventRecord(ev_join, s_side);

    // main stream: feature GEMM with fused si/sj scores
    {
        dim3 grid(FDIM / 128, (N + 127) / 128);
        k_gemm_h<<<grid, 256>>>(X, W, bw, A, N);
    }

    // join, then aggregate + output
    cudaStreamWaitEvent(0, ev_join, 0);
    k_agg<<<(N + 7) / 8, 256>>>(gmm, bet, ba, N);
    k_out<<<(N + 31) / 32, 256>>>(Wout, bout, out, N);
}